// round 12
// baseline (speedup 1.0000x reference)
#include <cuda_runtime.h>
#include <cuda_fp16.h>
#include <cstdint>

// Problem constants
#define BB 4
#define SS 2048
#define DD 1024

// Scratch (allocation-free rule: __device__ globals). fp16 operands, fp32 sums.
__device__ __half g_x[BB * SS * DD];          // 16 MB  X in fp16
__device__ __half g_q[BB * SS * DD];          // 16 MB
__device__ __half g_k[BB * SS * DD];          // 16 MB
__device__ __half g_vt[BB * SS * DD];         // 16 MB (V^T per batch: [D, S])
__device__ __half g_wt[3 * DD * DD];          // 6 MB  (W^T)
__device__ __half g_p[(size_t)BB * SS * SS];  // 32 MB: unnormalized exp(scores)
__device__ float g_rs[(size_t)BB * SS * 16];  // per-row per-coltile partial sums

// ---------------------------------------------------------------------------
// fp16 mma.sync GEMM (f32 accum): C = A[M,K] * B[N,K]^T, A/B fp16 K-contig.
// CTA tile 256x128, 256 threads (8 warps of 64x64), 1 CTA/SM, KT=32 halves,
// 6-stage cp.async (prefetch distance 5), single __syncthreads per k-tile.
// Rationale: 11 MAC per smem byte (vs 7.7 at 128x128/32x64) -- smem crossbar
// was the R11 binder; L2 demand per SM halves too.
// ---------------------------------------------------------------------------
#define TM 256                                  // CTA rows
#define TN 128                                  // CTA cols
#define KT 32                                   // halves per stage
#define STAGES 6
#define ROWB 80                                 // bytes per row (64 data + 16 pad)
#define STAGE_BYTES ((TM + TN) * ROWB)          // 30720
#define SMEM_BYTES (STAGES * STAGE_BYTES)       // 184320

#define EPI_HALF  0
#define EPI_EXP   1
#define EPI_SCALE 2
#define EPI_VT    3

__device__ __forceinline__ uint32_t smem_u32(const void* p) {
    uint32_t a;
    asm("{ .reg .u64 t; cvta.to.shared.u64 t, %1; cvt.u32.u64 %0, t; }"
        : "=r"(a) : "l"(p));
    return a;
}
__device__ __forceinline__ void cp16(uint32_t dst, const void* src) {
    asm volatile("cp.async.cg.shared.global [%0], [%1], 16;"
                 :: "r"(dst), "l"(src) : "memory");
}
__device__ __forceinline__ void ldsm4(uint32_t* d, uint32_t addr) {
    asm volatile("ldmatrix.sync.aligned.m8n8.x4.shared.b16 {%0,%1,%2,%3}, [%4];"
                 : "=r"(d[0]), "=r"(d[1]), "=r"(d[2]), "=r"(d[3]) : "r"(addr));
}
__device__ __forceinline__ void mma_f16(float* c, const uint32_t* a,
                                        uint32_t b0, uint32_t b1) {
    asm volatile(
        "mma.sync.aligned.m16n8k16.row.col.f32.f16.f16.f32 "
        "{%0,%1,%2,%3}, {%4,%5,%6,%7}, {%8,%9}, {%0,%1,%2,%3};"
        : "+f"(c[0]), "+f"(c[1]), "+f"(c[2]), "+f"(c[3])
        : "r"(a[0]), "r"(a[1]), "r"(a[2]), "r"(a[3]), "r"(b0), "r"(b1));
}

// EPI_VT: srow = s-offset within batch; ldC = SS; Cv pre-offset to batch.
// EPI_SCALE: rsp = g_rs + (b*SS + bm)*16. EPI_EXP: diag = masking possible.
template<int EPI>
__device__ __forceinline__ void tc_gemm_body(
    const __half* __restrict__ A, const __half* __restrict__ B, void* __restrict__ Cv,
    int ldA, int ldB, int ldC, int kmax, int bm, int bn, char* smem,
    float* rs_out, const float* rsp, int srow, bool diag)
{
    const int tid = threadIdx.x;        // 0..255
    const int wid = tid >> 5;           // 0..7
    const int lid = tid & 31;
    const int gid = lid >> 2;
    const int tq  = lid & 3;
    const int wm  = wid >> 1;           // 0..3 -> 64-row slice
    const int wn  = wid & 1;            // 0..1 -> 64-col half
    const uint32_t sb = smem_u32(smem);

    __shared__ float rsumv[TM];
    if constexpr (EPI == EPI_SCALE) {
        // Cooperative row reciprocals. Rows whose tiles beyond their causal
        // length have zero partials, so summing kmax>>7 tiles is exact.
        const int ntl = kmax >> 7;
        const float* p = rsp + (size_t)tid * 16;
        float s = 0.f;
        for (int t = 0; t < ntl; t++) s += p[t];
        rsumv[tid] = 1.f / s;
    }

    // cp.async loader: 384 rows x 4 chunks = 6 per thread.
    // Rows 0..TM-1 = A, rows TM..TM+TN-1 = B.
    const int lrow = tid >> 2;          // 0..63
    const int lch  = tid & 3;
    const __half* ag = A + (size_t)(bm + lrow) * ldA + lch * 8;
    const __half* bg = B + (size_t)(bn + lrow) * ldB + lch * 8;
    const uint32_t s_off = (uint32_t)(lrow * ROWB + lch * 16);

    const int nkt = kmax / KT;          // >= 8 always

    // Prologue: issue stages 0..STAGES-2 (5 in flight)
    #pragma unroll
    for (int s = 0; s < STAGES - 1; s++) {
        const uint32_t st = sb + (uint32_t)s * STAGE_BYTES;
        const __half* ag2 = ag + (size_t)s * KT;
        const __half* bg2 = bg + (size_t)s * KT;
        #pragma unroll
        for (int j = 0; j < 4; j++)      // A: rows lrow + 64j
            cp16(st + s_off + (uint32_t)(64 * j * ROWB),
                 ag2 + (size_t)(64 * j) * ldA);
        #pragma unroll
        for (int j = 0; j < 2; j++)      // B: rows TM + lrow + 64j
            cp16(st + (uint32_t)(TM * ROWB) + s_off + (uint32_t)(64 * j * ROWB),
                 bg2 + (size_t)(64 * j) * ldB);
        asm volatile("cp.async.commit_group;" ::: "memory");
    }

    // ldmatrix lane addressing: sub&1 -> +8 rows, sub&2 -> +8 k halves (16B).
    const int sub = lid >> 3;
    const int rr  = lid & 7;
    const int rowsel = ((sub & 1) << 3) + rr;
    const uint32_t kselb = (uint32_t)((sub & 2) << 3);   // 0 or 16 bytes
    const uint32_t aL = (uint32_t)((wm * 64 + rowsel) * ROWB) + kselb;
    const uint32_t bL = (uint32_t)(TM * ROWB) +
                        (uint32_t)((wn * 64 + rowsel) * ROWB) + kselb;

    float acc[4][8][4];
    #pragma unroll
    for (int mt = 0; mt < 4; mt++)
        #pragma unroll
        for (int nt = 0; nt < 8; nt++)
            #pragma unroll
            for (int r = 0; r < 4; r++) acc[mt][nt][r] = 0.f;

    for (int kt = 0; kt < nkt; kt++) {
        asm volatile("cp.async.wait_group %0;" :: "n"(STAGES - 2) : "memory");
        __syncthreads();

        // Issue-early prefetch of stage kt+STAGES-1.
        if (kt + STAGES - 1 < nkt) {
            const int s = kt + STAGES - 1;
            const uint32_t st = sb + (uint32_t)(s % STAGES) * STAGE_BYTES;
            const __half* ag2 = ag + (size_t)s * KT;
            const __half* bg2 = bg + (size_t)s * KT;
            #pragma unroll
            for (int j = 0; j < 4; j++)
                cp16(st + s_off + (uint32_t)(64 * j * ROWB),
                     ag2 + (size_t)(64 * j) * ldA);
            #pragma unroll
            for (int j = 0; j < 2; j++)
                cp16(st + (uint32_t)(TM * ROWB) + s_off + (uint32_t)(64 * j * ROWB),
                     bg2 + (size_t)(64 * j) * ldB);
        }
        asm volatile("cp.async.commit_group;" ::: "memory");

        const uint32_t sbase = sb + (uint32_t)(kt % STAGES) * STAGE_BYTES;
        #pragma unroll
        for (int ks = 0; ks < 2; ks++) {          // two k16 blocks per KT=32
            uint32_t af[4][4], bf[4][4];
            #pragma unroll
            for (int mt = 0; mt < 4; mt++)
                ldsm4(af[mt], sbase + aL + (uint32_t)(mt * 16 * ROWB) + ks * 32u);
            #pragma unroll
            for (int np = 0; np < 4; np++)
                ldsm4(bf[np], sbase + bL + (uint32_t)(np * 16 * ROWB) + ks * 32u);
            #pragma unroll
            for (int mt = 0; mt < 4; mt++)
                #pragma unroll
                for (int np = 0; np < 4; np++) {
                    mma_f16(acc[mt][2 * np],     af[mt], bf[np][0], bf[np][2]);
                    mma_f16(acc[mt][2 * np + 1], af[mt], bf[np][1], bf[np][3]);
                }
        }
    }

    // ------------------------------- Epilogues -------------------------------
    if constexpr (EPI == EPI_HALF) {
        __half* C = (__half*)Cv;
        #pragma unroll
        for (int mt = 0; mt < 4; mt++) {
            const int r0 = bm + wm * 64 + mt * 16 + gid;
            #pragma unroll
            for (int nt = 0; nt < 8; nt++) {
                const int c0 = bn + wn * 64 + nt * 8 + tq * 2;
                *reinterpret_cast<__half2*>(C + (size_t)r0 * ldC + c0) =
                    __floats2half2_rn(acc[mt][nt][0], acc[mt][nt][1]);
                *reinterpret_cast<__half2*>(C + (size_t)(r0 + 8) * ldC + c0) =
                    __floats2half2_rn(acc[mt][nt][2], acc[mt][nt][3]);
            }
        }
    }
    if constexpr (EPI == EPI_VT) {
        // Stage C tile (256 s-rows x 128 d-cols) into smem as [d][s], then
        // write coalesced transposed rows to Cv (= g_vt batch base), ldC = SS.
        asm volatile("cp.async.wait_group 0;" ::: "memory");
        __syncthreads();                 // pipeline smem reuse is now safe
        __half* tb = (__half*)smem;      // [128][SPAD]
        const int SPAD = 264;            // halves; 528B rows, 16B-aligned
        #pragma unroll
        for (int mt = 0; mt < 4; mt++) {
            const int r0 = wm * 64 + mt * 16 + gid;     // local s row
            #pragma unroll
            for (int nt = 0; nt < 8; nt++) {
                const int c0 = wn * 64 + nt * 8 + tq * 2;   // local d col
                tb[(c0)     * SPAD + r0]     = __float2half_rn(acc[mt][nt][0]);
                tb[(c0 + 1) * SPAD + r0]     = __float2half_rn(acc[mt][nt][1]);
                tb[(c0)     * SPAD + r0 + 8] = __float2half_rn(acc[mt][nt][2]);
                tb[(c0 + 1) * SPAD + r0 + 8] = __float2half_rn(acc[mt][nt][3]);
            }
        }
        __syncthreads();
        __half* C = (__half*)Cv;
        const int d  = tid >> 1;                  // output row (D dim)
        const int s0 = (tid & 1) * 128;           // s-range half
        __half* orow = C + (size_t)(bn + d) * ldC + srow + s0;
        #pragma unroll
        for (int j = 0; j < 16; j++)              // 16 x 8 halves = 128 halves
            *reinterpret_cast<uint4*>(orow + j * 8) =
                *reinterpret_cast<uint4*>(tb + d * SPAD + s0 + j * 8);
    }
    if constexpr (EPI == EPI_EXP) {
        __half* C = (__half*)Cv;
        __shared__ float s2[2][TM];
        const float inv = 0.03125f;         // 1/sqrt(1024)
        #pragma unroll
        for (int mt = 0; mt < 4; mt++) {
            const int r0 = bm + wm * 64 + mt * 16 + gid;
            float sum0 = 0.f, sum1 = 0.f;
            #pragma unroll
            for (int nt = 0; nt < 8; nt++) {
                const int c0 = bn + wn * 64 + nt * 8 + tq * 2;
                __half h00 = __float2half_rn((!diag || c0     <= r0)     ? __expf(acc[mt][nt][0] * inv) : 0.f);
                __half h01 = __float2half_rn((!diag || c0 + 1 <= r0)     ? __expf(acc[mt][nt][1] * inv) : 0.f);
                __half h10 = __float2half_rn((!diag || c0     <= r0 + 8) ? __expf(acc[mt][nt][2] * inv) : 0.f);
                __half h11 = __float2half_rn((!diag || c0 + 1 <= r0 + 8) ? __expf(acc[mt][nt][3] * inv) : 0.f);
                *reinterpret_cast<__half2*>(C + (size_t)r0 * ldC + c0) = __halves2half2(h00, h01);
                *reinterpret_cast<__half2*>(C + (size_t)(r0 + 8) * ldC + c0) = __halves2half2(h10, h11);
                sum0 += __half2float(h00) + __half2float(h01);
                sum1 += __half2float(h10) + __half2float(h11);
            }
            #pragma unroll
            for (int off = 1; off <= 2; off <<= 1) {
                sum0 += __shfl_xor_sync(0xffffffffu, sum0, off);
                sum1 += __shfl_xor_sync(0xffffffffu, sum1, off);
            }
            if (tq == 0) {
                s2[wn][wm * 64 + mt * 16 + gid]     = sum0;
                s2[wn][wm * 64 + mt * 16 + gid + 8] = sum1;
            }
        }
        __syncthreads();
        rs_out[(size_t)tid * 16] = s2[0][tid] + s2[1][tid];
    }
    if constexpr (EPI == EPI_SCALE) {
        float* C = (float*)Cv;
        #pragma unroll
        for (int mt = 0; mt < 4; mt++) {
            const int lr0 = wm * 64 + mt * 16 + gid;     // local row
            const int r0 = bm + lr0;
            const float sc0 = rsumv[lr0];
            const float sc1 = rsumv[lr0 + 8];
            #pragma unroll
            for (int nt = 0; nt < 8; nt++) {
                const int c0 = bn + wn * 64 + nt * 8 + tq * 2;
                *reinterpret_cast<float2*>(C + (size_t)r0 * ldC + c0) =
                    make_float2(acc[mt][nt][0] * sc0, acc[mt][nt][1] * sc0);
                *reinterpret_cast<float2*>(C + (size_t)(r0 + 8) * ldC + c0) =
                    make_float2(acc[mt][nt][2] * sc1, acc[mt][nt][3] * sc1);
            }
        }
    }
}

// ---------------------------------------------------------------------------
// GEMM kernel wrappers
// ---------------------------------------------------------------------------
__global__ __launch_bounds__(256, 1) void qkv_tc() {
    extern __shared__ __align__(16) char smem[];
    const int z = blockIdx.z;
    const __half* Bz = g_wt + (size_t)z * DD * DD;
    const int bm = blockIdx.y * TM;
    if (z == 2) {
        // V: write transposed directly into g_vt (per-batch [D, S]).
        const int batch = bm >> 11;      // / SS
        const int srow  = bm & (SS - 1);
        tc_gemm_body<EPI_VT>(g_x, Bz, g_vt + (size_t)batch * SS * DD,
                             DD, DD, SS, DD, bm, blockIdx.x * TN, smem,
                             nullptr, nullptr, srow, false);
    } else {
        __half* Cz = (z == 0) ? g_q : g_k;
        tc_gemm_body<EPI_HALF>(g_x, Bz, Cz, DD, DD, DD, DD,
                               bm, blockIdx.x * TN, smem,
                               nullptr, nullptr, 0, false);
    }
}

// Triangular tiles over (256-row, 128-col): per batch sum(2by+2) = 72 tiles.
__global__ __launch_bounds__(256, 1) void scores_tc() {
    extern __shared__ __align__(16) char smem[];
    const int t = blockIdx.x;
    int by = (int)((sqrtf(4.f * (float)t + 1.f) - 1.f) * 0.5f);
    while ((by + 1) * (by + 2) <= t) by++;        // cum(by) = by^2 + by
    while (by * (by + 1) > t) by--;
    const int bx = t - by * (by + 1);             // 0 .. 2by+1
    size_t b = blockIdx.z;
    float* rs = g_rs + ((size_t)(b * SS + by * TM)) * 16 + bx;
    const bool diag = (bx >= 2 * by);
    tc_gemm_body<EPI_EXP>(g_q + b * SS * DD, g_k + b * SS * DD,
                          g_p + b * (size_t)SS * SS, DD, DD, SS, DD,
                          by * TM, bx * TN, smem, rs, nullptr, 0, diag);
}

__global__ __launch_bounds__(256, 1) void pv_tc(float* __restrict__ out) {
    extern __shared__ __align__(16) char smem[];
    size_t b = blockIdx.z;
    // Heavy-first: reverse block-row order so large-kmax tiles start in wave 1.
    const int byt = (int)gridDim.y - 1 - (int)blockIdx.y;
    int kmax = (byt + 1) * TM;
    if (kmax > SS) kmax = SS;
    const float* rsp = g_rs + ((size_t)(b * SS + byt * TM)) * 16;
    tc_gemm_body<EPI_SCALE>(g_p + b * (size_t)SS * SS, g_vt + b * SS * DD,
                            out + b * SS * DD, SS, SS, DD, kmax,
                            byt * TM, blockIdx.x * TN, smem,
                            nullptr, rsp, 0, false);
}

// ---------------------------------------------------------------------------
// Staging: convert X to fp16 once. 8 floats -> 8 halves (16B store) per thread.
// ---------------------------------------------------------------------------
__global__ __launch_bounds__(256) void stage_x(const float* __restrict__ x) {
    const size_t i = ((size_t)blockIdx.x * 256 + threadIdx.x) * 8;
    float4 v0 = *reinterpret_cast<const float4*>(x + i);
    float4 v1 = *reinterpret_cast<const float4*>(x + i + 4);
    __half2 h[4];
    h[0] = __floats2half2_rn(v0.x, v0.y);
    h[1] = __floats2half2_rn(v0.z, v0.w);
    h[2] = __floats2half2_rn(v1.x, v1.y);
    h[3] = __floats2half2_rn(v1.z, v1.w);
    *reinterpret_cast<uint4*>(g_x + i) = *reinterpret_cast<uint4*>(h);
}

// ---------------------------------------------------------------------------
// W transpose: g_wt[z][dout][din] = W[z][din][dout], fp16.
// ---------------------------------------------------------------------------
__global__ void transpose_w(const float* __restrict__ Wq,
                            const float* __restrict__ Wk,
                            const float* __restrict__ Wv) {
    const float* in = (blockIdx.z == 0) ? Wq : (blockIdx.z == 1) ? Wk : Wv;
    __half* out = g_wt + (size_t)blockIdx.z * DD * DD;
    __shared__ float t[32][33];
    const int tx = threadIdx.x, ty = threadIdx.y;
    const int bx = blockIdx.x * 32, by = blockIdx.y * 32;
    #pragma unroll
    for (int i = 0; i < 32; i += 8)
        t[ty + i][tx] = in[(size_t)(by + ty + i) * DD + bx + tx];
    __syncthreads();
    #pragma unroll
    for (int i = 0; i < 32; i += 8)
        out[(size_t)(bx + ty + i) * DD + by + tx] = __float2half_rn(t[tx][ty + i]);
}

// ---------------------------------------------------------------------------
extern "C" void kernel_launch(void* const* d_in, const int* in_sizes, int n_in,
                              void* d_out, int out_size)
{
    (void)in_sizes; (void)n_in; (void)out_size;
    const float* x  = (const float*)d_in[0];
    const float* Wq = (const float*)d_in[1];
    const float* Wk = (const float*)d_in[2];
    const float* Wv = (const float*)d_in[3];
    float* out = (float*)d_out;

    cudaFuncSetAttribute(qkv_tc,    cudaFuncAttributeMaxDynamicSharedMemorySize, SMEM_BYTES);
    cudaFuncSetAttribute(scores_tc, cudaFuncAttributeMaxDynamicSharedMemorySize, SMEM_BYTES);
    cudaFuncSetAttribute(pv_tc,     cudaFuncAttributeMaxDynamicSharedMemorySize, SMEM_BYTES);

    dim3 t32(32, 8);
    stage_x<<<dim3((BB * SS * DD) / (256 * 8)), 256>>>(x);
    transpose_w<<<dim3(DD / 32, DD / 32, 3), t32>>>(Wq, Wk, Wv);
    qkv_tc<<<dim3(DD / TN, (BB * SS) / TM, 3), 256, SMEM_BYTES>>>();
    scores_tc<<<dim3(72, 1, BB), 256, SMEM_BYTES>>>();
    pv_tc<<<dim3(DD / TN, SS / TM, BB), 256, SMEM_BYTES>>>(out);
}

// round 13
// speedup vs baseline: 1.1486x; 1.1486x over previous
#include <cuda_runtime.h>
#include <cuda_fp16.h>
#include <cstdint>

// Problem constants
#define BB 4
#define SS 2048
#define DD 1024

// Scratch (allocation-free rule: __device__ globals). fp16 operands, fp32 sums.
__device__ __half g_x[BB * SS * DD];          // 16 MB  X in fp16
__device__ __half g_q[BB * SS * DD];          // 16 MB
__device__ __half g_k[BB * SS * DD];          // 16 MB
__device__ __half g_vt[BB * SS * DD];         // 16 MB (V^T per batch: [D, S])
__device__ __half g_wt[3 * DD * DD];          // 6 MB  (W^T)
__device__ __half g_p[(size_t)BB * SS * SS];  // 32 MB: unnormalized exp(scores)
__device__ float g_rs[(size_t)BB * SS * 16];  // per-row per-coltile partial sums

// ---------------------------------------------------------------------------
// fp16 mma.sync GEMM (f32 accum): C = A[M,K] * B[N,K]^T, A/B fp16 K-contig.
// Block 128x128, 256 threads (8 warps of 32x64), 2 CTAs/SM, KT=32 halves,
// 5-stage cp.async (prefetch distance 4), single __syncthreads per k-tile.
// R12 lesson: the loop is latency/occupancy-bound, not smem-bound -- keep the
// 2-CTA shape and deepen the pipeline instead of growing the tile.
// ---------------------------------------------------------------------------
#define TILE 128
#define KT 32                                   // halves per stage
#define STAGES 5
#define ROWB 80                                 // bytes per row (64 data + 16 pad)
#define STAGE_BYTES (2 * TILE * ROWB)           // 20480
#define SMEM_BYTES (STAGES * STAGE_BYTES)       // 102400

#define EPI_HALF  0
#define EPI_EXP   1
#define EPI_SCALE 2
#define EPI_VT    3

__device__ __forceinline__ uint32_t smem_u32(const void* p) {
    uint32_t a;
    asm("{ .reg .u64 t; cvta.to.shared.u64 t, %1; cvt.u32.u64 %0, t; }"
        : "=r"(a) : "l"(p));
    return a;
}
__device__ __forceinline__ void cp16(uint32_t dst, const void* src) {
    asm volatile("cp.async.cg.shared.global [%0], [%1], 16;"
                 :: "r"(dst), "l"(src) : "memory");
}
__device__ __forceinline__ void ldsm4(uint32_t* d, uint32_t addr) {
    asm volatile("ldmatrix.sync.aligned.m8n8.x4.shared.b16 {%0,%1,%2,%3}, [%4];"
                 : "=r"(d[0]), "=r"(d[1]), "=r"(d[2]), "=r"(d[3]) : "r"(addr));
}
__device__ __forceinline__ void mma_f16(float* c, const uint32_t* a,
                                        uint32_t b0, uint32_t b1) {
    asm volatile(
        "mma.sync.aligned.m16n8k16.row.col.f32.f16.f16.f32 "
        "{%0,%1,%2,%3}, {%4,%5,%6,%7}, {%8,%9}, {%0,%1,%2,%3};"
        : "+f"(c[0]), "+f"(c[1]), "+f"(c[2]), "+f"(c[3])
        : "r"(a[0]), "r"(a[1]), "r"(a[2]), "r"(a[3]), "r"(b0), "r"(b1));
}

// EPI_VT: srow = s-offset within batch; ldC = SS; Cv pre-offset to batch.
// EPI_SCALE: rsp = g_rs + (b*SS + byt*128)*16, row partial base.
template<int EPI>
__device__ __forceinline__ void tc_gemm_body(
    const __half* __restrict__ A, const __half* __restrict__ B, void* __restrict__ Cv,
    int ldA, int ldB, int ldC, int kmax, int bm, int bn, char* smem,
    float* rs_out, const float* rsp, int srow)
{
    const int tid = threadIdx.x;        // 0..255
    const int wid = tid >> 5;           // 0..7
    const int lid = tid & 31;
    const int gid = lid >> 2;
    const int tq  = lid & 3;
    const int wm  = wid >> 1;           // 0..3 -> 32-row slice
    const int wn  = wid & 1;            // 0..1 -> 64-col half
    const uint32_t sb = smem_u32(smem);

    __shared__ float rsumv[TILE];
    if constexpr (EPI == EPI_SCALE) {
        // Cooperative row-reciprocal computation.
        if (tid < TILE) {
            const int ntl = kmax >> 7;          // tiles contributing to this row
            const float* p = rsp + (size_t)tid * 16;
            float s = 0.f;
            for (int t = 0; t < ntl; t++) s += p[t];
            rsumv[tid] = 1.f / s;
        }
    }

    // cp.async loader: thread -> (row = tid>>2 (+64j), 16B chunk = tid&3)
    const int lrow = tid >> 2;          // 0..63
    const int lch  = tid & 3;
    const __half* ag = A + (size_t)(bm + lrow) * ldA + lch * 8;
    const __half* bg = B + (size_t)(bn + lrow) * ldB + lch * 8;
    const uint32_t s_off = (uint32_t)(lrow * ROWB + lch * 16);

    const int nkt = kmax / KT;          // >= 4 always

    // Prologue: issue stages 0..STAGES-2 (4 in flight)
    #pragma unroll
    for (int s = 0; s < STAGES - 1; s++) {
        uint32_t da = sb + (uint32_t)s * STAGE_BYTES + s_off;
        uint32_t db = da + (uint32_t)TILE * ROWB;
        const __half* ag2 = ag + (size_t)s * KT;
        const __half* bg2 = bg + (size_t)s * KT;
        #pragma unroll
        for (int j = 0; j < 2; j++) {
            cp16(da + (uint32_t)(64 * j * ROWB), ag2 + (size_t)(64 * j) * ldA);
            cp16(db + (uint32_t)(64 * j * ROWB), bg2 + (size_t)(64 * j) * ldB);
        }
        asm volatile("cp.async.commit_group;" ::: "memory");
    }

    // ldmatrix lane addressing: sub&1 -> +8 rows, sub&2 -> +8 k halves (16B).
    const int sub = lid >> 3;
    const int rr  = lid & 7;
    const int rowsel = ((sub & 1) << 3) + rr;
    const uint32_t kselb = (uint32_t)((sub & 2) << 3);   // 0 or 16 bytes
    const uint32_t aL = (uint32_t)((wm * 32 + rowsel) * ROWB) + kselb;
    const uint32_t bL = (uint32_t)(TILE * ROWB) +
                        (uint32_t)((wn * 64 + rowsel) * ROWB) + kselb;

    float acc[2][8][4];
    #pragma unroll
    for (int mt = 0; mt < 2; mt++)
        #pragma unroll
        for (int nt = 0; nt < 8; nt++)
            #pragma unroll
            for (int r = 0; r < 4; r++) acc[mt][nt][r] = 0.f;

    for (int kt = 0; kt < nkt; kt++) {
        asm volatile("cp.async.wait_group %0;" :: "n"(STAGES - 2) : "memory");
        __syncthreads();

        // Issue-early prefetch of stage kt+STAGES-1.
        if (kt + STAGES - 1 < nkt) {
            const int s = kt + STAGES - 1;
            uint32_t da = sb + (uint32_t)(s % STAGES) * STAGE_BYTES + s_off;
            uint32_t db = da + (uint32_t)TILE * ROWB;
            const __half* ag2 = ag + (size_t)s * KT;
            const __half* bg2 = bg + (size_t)s * KT;
            #pragma unroll
            for (int j = 0; j < 2; j++) {
                cp16(da + (uint32_t)(64 * j * ROWB), ag2 + (size_t)(64 * j) * ldA);
                cp16(db + (uint32_t)(64 * j * ROWB), bg2 + (size_t)(64 * j) * ldB);
            }
        }
        asm volatile("cp.async.commit_group;" ::: "memory");

        const uint32_t sbase = sb + (uint32_t)(kt % STAGES) * STAGE_BYTES;
        #pragma unroll
        for (int ks = 0; ks < 2; ks++) {          // two k16 blocks per KT=32
            uint32_t af[2][4], bf[4][4];
            #pragma unroll
            for (int mt = 0; mt < 2; mt++)
                ldsm4(af[mt], sbase + aL + (uint32_t)(mt * 16 * ROWB) + ks * 32u);
            #pragma unroll
            for (int np = 0; np < 4; np++)
                ldsm4(bf[np], sbase + bL + (uint32_t)(np * 16 * ROWB) + ks * 32u);
            #pragma unroll
            for (int mt = 0; mt < 2; mt++)
                #pragma unroll
                for (int np = 0; np < 4; np++) {
                    mma_f16(acc[mt][2 * np],     af[mt], bf[np][0], bf[np][2]);
                    mma_f16(acc[mt][2 * np + 1], af[mt], bf[np][1], bf[np][3]);
                }
        }
    }

    // ------------------------------- Epilogues -------------------------------
    if constexpr (EPI == EPI_HALF) {
        __half* C = (__half*)Cv;
        #pragma unroll
        for (int mt = 0; mt < 2; mt++) {
            const int r0 = bm + wm * 32 + mt * 16 + gid;
            #pragma unroll
            for (int nt = 0; nt < 8; nt++) {
                const int c0 = bn + wn * 64 + nt * 8 + tq * 2;
                *reinterpret_cast<__half2*>(C + (size_t)r0 * ldC + c0) =
                    __floats2half2_rn(acc[mt][nt][0], acc[mt][nt][1]);
                *reinterpret_cast<__half2*>(C + (size_t)(r0 + 8) * ldC + c0) =
                    __floats2half2_rn(acc[mt][nt][2], acc[mt][nt][3]);
            }
        }
    }
    if constexpr (EPI == EPI_VT) {
        // Stage C tile (128x128 half) into smem as [col][row], then write
        // coalesced transposed rows to Cv (= g_vt batch base), ldC = SS.
        asm volatile("cp.async.wait_group 0;" ::: "memory");
        __syncthreads();                 // pipeline smem reuse is now safe
        __half* tb = (__half*)smem;      // [128][SPAD]
        const int SPAD = 136;            // halves; 272B row -> 16B-aligned rows
        #pragma unroll
        for (int mt = 0; mt < 2; mt++) {
            const int r0 = wm * 32 + mt * 16 + gid;     // local row
            #pragma unroll
            for (int nt = 0; nt < 8; nt++) {
                const int c0 = wn * 64 + nt * 8 + tq * 2;
                tb[(c0)     * SPAD + r0]     = __float2half_rn(acc[mt][nt][0]);
                tb[(c0 + 1) * SPAD + r0]     = __float2half_rn(acc[mt][nt][1]);
                tb[(c0)     * SPAD + r0 + 8] = __float2half_rn(acc[mt][nt][2]);
                tb[(c0 + 1) * SPAD + r0 + 8] = __float2half_rn(acc[mt][nt][3]);
            }
        }
        __syncthreads();
        __half* C = (__half*)Cv;
        const int d  = tid >> 1;                  // output row (D dim)
        const int s0 = (tid & 1) * 64;            // s-range half
        __half* orow = C + (size_t)(bn + d) * ldC + srow + s0;
        #pragma unroll
        for (int j = 0; j < 8; j++) {             // 8 x 8 halves = 64 halves
            *reinterpret_cast<uint4*>(orow + j * 8) =
                *reinterpret_cast<uint4*>(tb + d * SPAD + s0 + j * 8);
        }
    }
    if constexpr (EPI == EPI_EXP) {
        __half* C = (__half*)Cv;
        __shared__ float s2[2][TILE];
        const float inv = 0.03125f;         // 1/sqrt(1024)
        const bool diag = (bm == bn);
        #pragma unroll
        for (int mt = 0; mt < 2; mt++) {
            const int r0 = bm + wm * 32 + mt * 16 + gid;
            float sum0 = 0.f, sum1 = 0.f;
            #pragma unroll
            for (int nt = 0; nt < 8; nt++) {
                const int c0 = bn + wn * 64 + nt * 8 + tq * 2;
                __half h00 = __float2half_rn((!diag || c0     <= r0)     ? __expf(acc[mt][nt][0] * inv) : 0.f);
                __half h01 = __float2half_rn((!diag || c0 + 1 <= r0)     ? __expf(acc[mt][nt][1] * inv) : 0.f);
                __half h10 = __float2half_rn((!diag || c0     <= r0 + 8) ? __expf(acc[mt][nt][2] * inv) : 0.f);
                __half h11 = __float2half_rn((!diag || c0 + 1 <= r0 + 8) ? __expf(acc[mt][nt][3] * inv) : 0.f);
                *reinterpret_cast<__half2*>(C + (size_t)r0 * ldC + c0) = __halves2half2(h00, h01);
                *reinterpret_cast<__half2*>(C + (size_t)(r0 + 8) * ldC + c0) = __halves2half2(h10, h11);
                sum0 += __half2float(h00) + __half2float(h01);
                sum1 += __half2float(h10) + __half2float(h11);
            }
            #pragma unroll
            for (int off = 1; off <= 2; off <<= 1) {
                sum0 += __shfl_xor_sync(0xffffffffu, sum0, off);
                sum1 += __shfl_xor_sync(0xffffffffu, sum1, off);
            }
            if (tq == 0) {
                s2[wn][wm * 32 + mt * 16 + gid]     = sum0;
                s2[wn][wm * 32 + mt * 16 + gid + 8] = sum1;
            }
        }
        __syncthreads();
        if (tid < TILE)
            rs_out[(size_t)tid * 16] = s2[0][tid] + s2[1][tid];
    }
    if constexpr (EPI == EPI_SCALE) {
        float* C = (float*)Cv;
        #pragma unroll
        for (int mt = 0; mt < 2; mt++) {
            const int lr0 = wm * 32 + mt * 16 + gid;     // local row
            const int r0 = bm + lr0;
            const float sc0 = rsumv[lr0];
            const float sc1 = rsumv[lr0 + 8];
            #pragma unroll
            for (int nt = 0; nt < 8; nt++) {
                const int c0 = bn + wn * 64 + nt * 8 + tq * 2;
                *reinterpret_cast<float2*>(C + (size_t)r0 * ldC + c0) =
                    make_float2(acc[mt][nt][0] * sc0, acc[mt][nt][1] * sc0);
                *reinterpret_cast<float2*>(C + (size_t)(r0 + 8) * ldC + c0) =
                    make_float2(acc[mt][nt][2] * sc1, acc[mt][nt][3] * sc1);
            }
        }
    }
}

// ---------------------------------------------------------------------------
// GEMM kernel wrappers
// ---------------------------------------------------------------------------
__global__ __launch_bounds__(256, 2) void qkv_tc() {
    extern __shared__ __align__(16) char smem[];
    const int z = blockIdx.z;
    const __half* Bz = g_wt + (size_t)z * DD * DD;
    const int bm = blockIdx.y * TILE;
    if (z == 2) {
        // V: write transposed directly into g_vt (per-batch [D, S]).
        const int batch = bm >> 11;      // / SS
        const int srow  = bm & (SS - 1);
        tc_gemm_body<EPI_VT>(g_x, Bz, g_vt + (size_t)batch * SS * DD,
                             DD, DD, SS, DD, bm, blockIdx.x * TILE, smem,
                             nullptr, nullptr, srow);
    } else {
        __half* Cz = (z == 0) ? g_q : g_k;
        tc_gemm_body<EPI_HALF>(g_x, Bz, Cz, DD, DD, DD, DD,
                               bm, blockIdx.x * TILE, smem,
                               nullptr, nullptr, 0);
    }
}

// Only lower-triangle tiles: grid.x = 16*17/2 = 136 per batch.
__global__ __launch_bounds__(256, 2) void scores_tc() {
    extern __shared__ __align__(16) char smem[];
    const int t = blockIdx.x;
    int by = (int)((sqrtf(8.f * (float)t + 1.f) - 1.f) * 0.5f);
    while ((by + 1) * (by + 2) / 2 <= t) by++;
    while (by * (by + 1) / 2 > t) by--;
    const int bx = t - by * (by + 1) / 2;
    size_t b = blockIdx.z;
    float* rs = g_rs + ((size_t)(b * SS + by * TILE)) * 16 + bx;
    tc_gemm_body<EPI_EXP>(g_q + b * SS * DD, g_k + b * SS * DD,
                          g_p + b * (size_t)SS * SS, DD, DD, SS, DD,
                          by * TILE, bx * TILE, smem, rs, nullptr, 0);
}

__global__ __launch_bounds__(256, 2) void pv_tc(float* __restrict__ out) {
    extern __shared__ __align__(16) char smem[];
    size_t b = blockIdx.z;
    // Heavy-first: reverse block-row order so large-kmax tiles start in wave 1.
    const int byt = (int)gridDim.y - 1 - (int)blockIdx.y;
    int kmax = (byt + 1) * TILE;
    if (kmax > SS) kmax = SS;
    const float* rsp = g_rs + ((size_t)(b * SS + byt * TILE)) * 16;
    tc_gemm_body<EPI_SCALE>(g_p + b * (size_t)SS * SS, g_vt + b * SS * DD,
                            out + b * SS * DD, SS, SS, DD, kmax,
                            byt * TILE, blockIdx.x * TILE, smem,
                            nullptr, rsp, 0);
}

// ---------------------------------------------------------------------------
// Staging: convert X to fp16 once. 8 floats -> 8 halves (16B store) per thread.
// ---------------------------------------------------------------------------
__global__ __launch_bounds__(256) void stage_x(const float* __restrict__ x) {
    const size_t i = ((size_t)blockIdx.x * 256 + threadIdx.x) * 8;
    float4 v0 = *reinterpret_cast<const float4*>(x + i);
    float4 v1 = *reinterpret_cast<const float4*>(x + i + 4);
    __half2 h[4];
    h[0] = __floats2half2_rn(v0.x, v0.y);
    h[1] = __floats2half2_rn(v0.z, v0.w);
    h[2] = __floats2half2_rn(v1.x, v1.y);
    h[3] = __floats2half2_rn(v1.z, v1.w);
    *reinterpret_cast<uint4*>(g_x + i) = *reinterpret_cast<uint4*>(h);
}

// ---------------------------------------------------------------------------
// W transpose: g_wt[z][dout][din] = W[z][din][dout], fp16.
// ---------------------------------------------------------------------------
__global__ void transpose_w(const float* __restrict__ Wq,
                            const float* __restrict__ Wk,
                            const float* __restrict__ Wv) {
    const float* in = (blockIdx.z == 0) ? Wq : (blockIdx.z == 1) ? Wk : Wv;
    __half* out = g_wt + (size_t)blockIdx.z * DD * DD;
    __shared__ float t[32][33];
    const int tx = threadIdx.x, ty = threadIdx.y;
    const int bx = blockIdx.x * 32, by = blockIdx.y * 32;
    #pragma unroll
    for (int i = 0; i < 32; i += 8)
        t[ty + i][tx] = in[(size_t)(by + ty + i) * DD + bx + tx];
    __syncthreads();
    #pragma unroll
    for (int i = 0; i < 32; i += 8)
        out[(size_t)(bx + ty + i) * DD + by + tx] = __float2half_rn(t[tx][ty + i]);
}

// ---------------------------------------------------------------------------
extern "C" void kernel_launch(void* const* d_in, const int* in_sizes, int n_in,
                              void* d_out, int out_size)
{
    (void)in_sizes; (void)n_in; (void)out_size;
    const float* x  = (const float*)d_in[0];
    const float* Wq = (const float*)d_in[1];
    const float* Wk = (const float*)d_in[2];
    const float* Wv = (const float*)d_in[3];
    float* out = (float*)d_out;

    cudaFuncSetAttribute(qkv_tc,    cudaFuncAttributeMaxDynamicSharedMemorySize, SMEM_BYTES);
    cudaFuncSetAttribute(scores_tc, cudaFuncAttributeMaxDynamicSharedMemorySize, SMEM_BYTES);
    cudaFuncSetAttribute(pv_tc,     cudaFuncAttributeMaxDynamicSharedMemorySize, SMEM_BYTES);

    dim3 t32(32, 8);
    stage_x<<<dim3((BB * SS * DD) / (256 * 8)), 256>>>(x);
    transpose_w<<<dim3(DD / 32, DD / 32, 3), t32>>>(Wq, Wk, Wv);
    qkv_tc<<<dim3(DD / TILE, (BB * SS) / TILE, 3), 256, SMEM_BYTES>>>();
    scores_tc<<<dim3(136, 1, BB), 256, SMEM_BYTES>>>();
    pv_tc<<<dim3(DD / TILE, SS / TILE, BB), 256, SMEM_BYTES>>>(out);
}

// round 14
// speedup vs baseline: 1.3014x; 1.1331x over previous
#include <cuda_runtime.h>
#include <cuda_fp16.h>
#include <cstdint>

// Problem constants
#define BB 4
#define SS 2048
#define DD 1024

// Scratch (allocation-free rule: __device__ globals). fp16 operands, fp32 sums.
__device__ __half g_x[BB * SS * DD];          // 16 MB  X in fp16
__device__ __half g_q[BB * SS * DD];          // 16 MB
__device__ __half g_k[BB * SS * DD];          // 16 MB
__device__ __half g_vt[BB * SS * DD];         // 16 MB (V^T per batch: [D, S])
__device__ __half g_wt[3 * DD * DD];          // 6 MB  (W^T)
__device__ __half g_p[(size_t)BB * SS * SS];  // 32 MB: unnormalized exp(scores)
__device__ float g_rs[(size_t)BB * SS * 16];  // per-row per-coltile partial sums

// ---------------------------------------------------------------------------
// fp16 mma.sync GEMM (f32 accum): C = A[M,K] * B[N,K]^T, A/B fp16 K-contig.
// Block 128x128, 256 threads (8 warps of 32x64), 2 CTAs/SM, KT=32 halves,
// 4-stage cp.async (prefetch distance 3), single __syncthreads per k-tile.
// R12 (bigger tile) and R13 (deeper pipeline) both regressed: this shape is
// the measured local optimum for mma.sync on this part. Do not perturb.
// ---------------------------------------------------------------------------
#define TILE 128
#define KT 32                                   // halves per stage
#define STAGES 4
#define ROWB 80                                 // bytes per row (64 data + 16 pad)
#define STAGE_BYTES (2 * TILE * ROWB)           // 20480
#define SMEM_BYTES (STAGES * STAGE_BYTES)       // 81920

#define EPI_HALF  0
#define EPI_EXP   1
#define EPI_SCALE 2
#define EPI_VT    3

__device__ __forceinline__ uint32_t smem_u32(const void* p) {
    uint32_t a;
    asm("{ .reg .u64 t; cvta.to.shared.u64 t, %1; cvt.u32.u64 %0, t; }"
        : "=r"(a) : "l"(p));
    return a;
}
__device__ __forceinline__ void cp16(uint32_t dst, const void* src) {
    asm volatile("cp.async.cg.shared.global [%0], [%1], 16;"
                 :: "r"(dst), "l"(src) : "memory");
}
__device__ __forceinline__ void ldsm4(uint32_t* d, uint32_t addr) {
    asm volatile("ldmatrix.sync.aligned.m8n8.x4.shared.b16 {%0,%1,%2,%3}, [%4];"
                 : "=r"(d[0]), "=r"(d[1]), "=r"(d[2]), "=r"(d[3]) : "r"(addr));
}
__device__ __forceinline__ void mma_f16(float* c, const uint32_t* a,
                                        uint32_t b0, uint32_t b1) {
    asm volatile(
        "mma.sync.aligned.m16n8k16.row.col.f32.f16.f16.f32 "
        "{%0,%1,%2,%3}, {%4,%5,%6,%7}, {%8,%9}, {%0,%1,%2,%3};"
        : "+f"(c[0]), "+f"(c[1]), "+f"(c[2]), "+f"(c[3])
        : "r"(a[0]), "r"(a[1]), "r"(a[2]), "r"(a[3]), "r"(b0), "r"(b1));
}

// EPI_VT: srow = s-offset within batch; ldC = SS; Cv pre-offset to batch.
// EPI_SCALE: rsp = g_rs + (b*SS + byt*128)*16, row partial base.
template<int EPI>
__device__ __forceinline__ void tc_gemm_body(
    const __half* __restrict__ A, const __half* __restrict__ B, void* __restrict__ Cv,
    int ldA, int ldB, int ldC, int kmax, int bm, int bn, char* smem,
    float* rs_out, const float* rsp, int srow)
{
    const int tid = threadIdx.x;        // 0..255
    const int wid = tid >> 5;           // 0..7
    const int lid = tid & 31;
    const int gid = lid >> 2;
    const int tq  = lid & 3;
    const int wm  = wid >> 1;           // 0..3 -> 32-row slice
    const int wn  = wid & 1;            // 0..1 -> 64-col half
    const uint32_t sb = smem_u32(smem);

    __shared__ float rsumv[TILE];
    if constexpr (EPI == EPI_SCALE) {
        // Cooperative row-reciprocal computation.
        if (tid < TILE) {
            const int ntl = kmax >> 7;          // tiles contributing to this row
            const float* p = rsp + (size_t)tid * 16;
            float s = 0.f;
            for (int t = 0; t < ntl; t++) s += p[t];
            rsumv[tid] = 1.f / s;
        }
    }

    // cp.async loader: thread -> (row = tid>>2 (+64j), 16B chunk = tid&3)
    const int lrow = tid >> 2;          // 0..63
    const int lch  = tid & 3;
    const __half* ag = A + (size_t)(bm + lrow) * ldA + lch * 8;
    const __half* bg = B + (size_t)(bn + lrow) * ldB + lch * 8;
    const uint32_t s_off = (uint32_t)(lrow * ROWB + lch * 16);

    const int nkt = kmax / KT;          // >= 4 always

    // Prologue: issue stages 0..STAGES-2 (3 in flight)
    #pragma unroll
    for (int s = 0; s < STAGES - 1; s++) {
        uint32_t da = sb + (uint32_t)s * STAGE_BYTES + s_off;
        uint32_t db = da + (uint32_t)TILE * ROWB;
        const __half* ag2 = ag + (size_t)s * KT;
        const __half* bg2 = bg + (size_t)s * KT;
        #pragma unroll
        for (int j = 0; j < 2; j++) {
            cp16(da + (uint32_t)(64 * j * ROWB), ag2 + (size_t)(64 * j) * ldA);
            cp16(db + (uint32_t)(64 * j * ROWB), bg2 + (size_t)(64 * j) * ldB);
        }
        asm volatile("cp.async.commit_group;" ::: "memory");
    }

    // ldmatrix lane addressing: sub&1 -> +8 rows, sub&2 -> +8 k halves (16B).
    const int sub = lid >> 3;
    const int rr  = lid & 7;
    const int rowsel = ((sub & 1) << 3) + rr;
    const uint32_t kselb = (uint32_t)((sub & 2) << 3);   // 0 or 16 bytes
    const uint32_t aL = (uint32_t)((wm * 32 + rowsel) * ROWB) + kselb;
    const uint32_t bL = (uint32_t)(TILE * ROWB) +
                        (uint32_t)((wn * 64 + rowsel) * ROWB) + kselb;

    float acc[2][8][4];
    #pragma unroll
    for (int mt = 0; mt < 2; mt++)
        #pragma unroll
        for (int nt = 0; nt < 8; nt++)
            #pragma unroll
            for (int r = 0; r < 4; r++) acc[mt][nt][r] = 0.f;

    for (int kt = 0; kt < nkt; kt++) {
        asm volatile("cp.async.wait_group %0;" :: "n"(STAGES - 2) : "memory");
        __syncthreads();

        // Issue-early prefetch of stage kt+STAGES-1.
        if (kt + STAGES - 1 < nkt) {
            const int s = kt + STAGES - 1;
            uint32_t da = sb + (uint32_t)(s % STAGES) * STAGE_BYTES + s_off;
            uint32_t db = da + (uint32_t)TILE * ROWB;
            const __half* ag2 = ag + (size_t)s * KT;
            const __half* bg2 = bg + (size_t)s * KT;
            #pragma unroll
            for (int j = 0; j < 2; j++) {
                cp16(da + (uint32_t)(64 * j * ROWB), ag2 + (size_t)(64 * j) * ldA);
                cp16(db + (uint32_t)(64 * j * ROWB), bg2 + (size_t)(64 * j) * ldB);
            }
        }
        asm volatile("cp.async.commit_group;" ::: "memory");

        const uint32_t sbase = sb + (uint32_t)(kt % STAGES) * STAGE_BYTES;
        #pragma unroll
        for (int ks = 0; ks < 2; ks++) {          // two k16 blocks per KT=32
            uint32_t af[2][4], bf[4][4];
            #pragma unroll
            for (int mt = 0; mt < 2; mt++)
                ldsm4(af[mt], sbase + aL + (uint32_t)(mt * 16 * ROWB) + ks * 32u);
            #pragma unroll
            for (int np = 0; np < 4; np++)
                ldsm4(bf[np], sbase + bL + (uint32_t)(np * 16 * ROWB) + ks * 32u);
            #pragma unroll
            for (int mt = 0; mt < 2; mt++)
                #pragma unroll
                for (int np = 0; np < 4; np++) {
                    mma_f16(acc[mt][2 * np],     af[mt], bf[np][0], bf[np][2]);
                    mma_f16(acc[mt][2 * np + 1], af[mt], bf[np][1], bf[np][3]);
                }
        }
    }

    // ------------------------------- Epilogues -------------------------------
    if constexpr (EPI == EPI_HALF) {
        __half* C = (__half*)Cv;
        #pragma unroll
        for (int mt = 0; mt < 2; mt++) {
            const int r0 = bm + wm * 32 + mt * 16 + gid;
            #pragma unroll
            for (int nt = 0; nt < 8; nt++) {
                const int c0 = bn + wn * 64 + nt * 8 + tq * 2;
                *reinterpret_cast<__half2*>(C + (size_t)r0 * ldC + c0) =
                    __floats2half2_rn(acc[mt][nt][0], acc[mt][nt][1]);
                *reinterpret_cast<__half2*>(C + (size_t)(r0 + 8) * ldC + c0) =
                    __floats2half2_rn(acc[mt][nt][2], acc[mt][nt][3]);
            }
        }
    }
    if constexpr (EPI == EPI_VT) {
        // Stage C tile (128x128 half) into smem as [col][row], then write
        // coalesced transposed rows to Cv (= g_vt batch base), ldC = SS.
        asm volatile("cp.async.wait_group 0;" ::: "memory");
        __syncthreads();                 // pipeline smem reuse is now safe
        __half* tb = (__half*)smem;      // [128][SPAD]
        const int SPAD = 136;            // halves; 272B row -> 16B-aligned rows
        #pragma unroll
        for (int mt = 0; mt < 2; mt++) {
            const int r0 = wm * 32 + mt * 16 + gid;     // local row
            #pragma unroll
            for (int nt = 0; nt < 8; nt++) {
                const int c0 = wn * 64 + nt * 8 + tq * 2;
                tb[(c0)     * SPAD + r0]     = __float2half_rn(acc[mt][nt][0]);
                tb[(c0 + 1) * SPAD + r0]     = __float2half_rn(acc[mt][nt][1]);
                tb[(c0)     * SPAD + r0 + 8] = __float2half_rn(acc[mt][nt][2]);
                tb[(c0 + 1) * SPAD + r0 + 8] = __float2half_rn(acc[mt][nt][3]);
            }
        }
        __syncthreads();
        __half* C = (__half*)Cv;
        const int d  = tid >> 1;                  // output row (D dim)
        const int s0 = (tid & 1) * 64;            // s-range half
        __half* orow = C + (size_t)(bn + d) * ldC + srow + s0;
        #pragma unroll
        for (int j = 0; j < 8; j++) {             // 8 x 8 halves = 64 halves
            *reinterpret_cast<uint4*>(orow + j * 8) =
                *reinterpret_cast<uint4*>(tb + d * SPAD + s0 + j * 8);
        }
    }
    if constexpr (EPI == EPI_EXP) {
        __half* C = (__half*)Cv;
        __shared__ float s2[2][TILE];
        const float inv = 0.03125f;         // 1/sqrt(1024)
        const bool diag = (bm == bn);
        #pragma unroll
        for (int mt = 0; mt < 2; mt++) {
            const int r0 = bm + wm * 32 + mt * 16 + gid;
            float sum0 = 0.f, sum1 = 0.f;
            #pragma unroll
            for (int nt = 0; nt < 8; nt++) {
                const int c0 = bn + wn * 64 + nt * 8 + tq * 2;
                __half h00 = __float2half_rn((!diag || c0     <= r0)     ? __expf(acc[mt][nt][0] * inv) : 0.f);
                __half h01 = __float2half_rn((!diag || c0 + 1 <= r0)     ? __expf(acc[mt][nt][1] * inv) : 0.f);
                __half h10 = __float2half_rn((!diag || c0     <= r0 + 8) ? __expf(acc[mt][nt][2] * inv) : 0.f);
                __half h11 = __float2half_rn((!diag || c0 + 1 <= r0 + 8) ? __expf(acc[mt][nt][3] * inv) : 0.f);
                *reinterpret_cast<__half2*>(C + (size_t)r0 * ldC + c0) = __halves2half2(h00, h01);
                *reinterpret_cast<__half2*>(C + (size_t)(r0 + 8) * ldC + c0) = __halves2half2(h10, h11);
                sum0 += __half2float(h00) + __half2float(h01);
                sum1 += __half2float(h10) + __half2float(h11);
            }
            #pragma unroll
            for (int off = 1; off <= 2; off <<= 1) {
                sum0 += __shfl_xor_sync(0xffffffffu, sum0, off);
                sum1 += __shfl_xor_sync(0xffffffffu, sum1, off);
            }
            if (tq == 0) {
                s2[wn][wm * 32 + mt * 16 + gid]     = sum0;
                s2[wn][wm * 32 + mt * 16 + gid + 8] = sum1;
            }
        }
        __syncthreads();
        if (tid < TILE)
            rs_out[(size_t)tid * 16] = s2[0][tid] + s2[1][tid];
    }
    if constexpr (EPI == EPI_SCALE) {
        float* C = (float*)Cv;
        #pragma unroll
        for (int mt = 0; mt < 2; mt++) {
            const int lr0 = wm * 32 + mt * 16 + gid;     // local row
            const int r0 = bm + lr0;
            const float sc0 = rsumv[lr0];
            const float sc1 = rsumv[lr0 + 8];
            #pragma unroll
            for (int nt = 0; nt < 8; nt++) {
                const int c0 = bn + wn * 64 + nt * 8 + tq * 2;
                *reinterpret_cast<float2*>(C + (size_t)r0 * ldC + c0) =
                    make_float2(acc[mt][nt][0] * sc0, acc[mt][nt][1] * sc0);
                *reinterpret_cast<float2*>(C + (size_t)(r0 + 8) * ldC + c0) =
                    make_float2(acc[mt][nt][2] * sc1, acc[mt][nt][3] * sc1);
            }
        }
    }
}

// ---------------------------------------------------------------------------
// GEMM kernel wrappers
// ---------------------------------------------------------------------------
__global__ __launch_bounds__(256, 2) void qkv_tc() {
    extern __shared__ __align__(16) char smem[];
    const int z = blockIdx.z;
    const __half* Bz = g_wt + (size_t)z * DD * DD;
    const int bm = blockIdx.y * TILE;
    if (z == 2) {
        // V: write transposed directly into g_vt (per-batch [D, S]).
        const int batch = bm >> 11;      // / SS
        const int srow  = bm & (SS - 1);
        tc_gemm_body<EPI_VT>(g_x, Bz, g_vt + (size_t)batch * SS * DD,
                             DD, DD, SS, DD, bm, blockIdx.x * TILE, smem,
                             nullptr, nullptr, srow);
    } else {
        __half* Cz = (z == 0) ? g_q : g_k;
        tc_gemm_body<EPI_HALF>(g_x, Bz, Cz, DD, DD, DD, DD,
                               bm, blockIdx.x * TILE, smem,
                               nullptr, nullptr, 0);
    }
}

// Only lower-triangle tiles: grid.x = 16*17/2 = 136 per batch.
__global__ __launch_bounds__(256, 2) void scores_tc() {
    extern __shared__ __align__(16) char smem[];
    const int t = blockIdx.x;
    int by = (int)((sqrtf(8.f * (float)t + 1.f) - 1.f) * 0.5f);
    while ((by + 1) * (by + 2) / 2 <= t) by++;
    while (by * (by + 1) / 2 > t) by--;
    const int bx = t - by * (by + 1) / 2;
    size_t b = blockIdx.z;
    float* rs = g_rs + ((size_t)(b * SS + by * TILE)) * 16 + bx;
    tc_gemm_body<EPI_EXP>(g_q + b * SS * DD, g_k + b * SS * DD,
                          g_p + b * (size_t)SS * SS, DD, DD, SS, DD,
                          by * TILE, bx * TILE, smem, rs, nullptr, 0);
}

__global__ __launch_bounds__(256, 2) void pv_tc(float* __restrict__ out) {
    extern __shared__ __align__(16) char smem[];
    size_t b = blockIdx.z;
    // Heavy-first: reverse block-row order so large-kmax tiles start in wave 1.
    const int byt = (int)gridDim.y - 1 - (int)blockIdx.y;
    int kmax = (byt + 1) * TILE;
    if (kmax > SS) kmax = SS;
    const float* rsp = g_rs + ((size_t)(b * SS + byt * TILE)) * 16;
    tc_gemm_body<EPI_SCALE>(g_p + b * (size_t)SS * SS, g_vt + b * SS * DD,
                            out + b * SS * DD, SS, SS, DD, kmax,
                            byt * TILE, blockIdx.x * TILE, smem,
                            nullptr, rsp, 0);
}

// ---------------------------------------------------------------------------
// Merged prologue: z<3 -> W^T transpose tile (fp32 -> fp16), z>=3 -> X convert.
// Both use 256 threads laid out as (32, 8).
// ---------------------------------------------------------------------------
__global__ void prep(const float* __restrict__ x,
                     const float* __restrict__ Wq,
                     const float* __restrict__ Wk,
                     const float* __restrict__ Wv) {
    const int z = blockIdx.z;
    if (z < 3) {
        const float* in = (z == 0) ? Wq : (z == 1) ? Wk : Wv;
        __half* out = g_wt + (size_t)z * DD * DD;
        __shared__ float t[32][33];
        const int tx = threadIdx.x, ty = threadIdx.y;
        const int bx = blockIdx.x * 32, by = blockIdx.y * 32;
        #pragma unroll
        for (int i = 0; i < 32; i += 8)
            t[ty + i][tx] = in[(size_t)(by + ty + i) * DD + bx + tx];
        __syncthreads();
        #pragma unroll
        for (int i = 0; i < 32; i += 8)
            out[(size_t)(bx + ty + i) * DD + by + tx] = __float2half_rn(t[tx][ty + i]);
    } else {
        // X convert: linear block id over (z-3, blockIdx.y, blockIdx.x).
        const int blk = (z - 3) * 1024 + blockIdx.y * 32 + blockIdx.x;
        const int tid = threadIdx.y * 32 + threadIdx.x;
        const size_t i = ((size_t)blk * 256 + tid) * 8;
        float4 v0 = *reinterpret_cast<const float4*>(x + i);
        float4 v1 = *reinterpret_cast<const float4*>(x + i + 4);
        __half2 h[4];
        h[0] = __floats2half2_rn(v0.x, v0.y);
        h[1] = __floats2half2_rn(v0.z, v0.w);
        h[2] = __floats2half2_rn(v1.x, v1.y);
        h[3] = __floats2half2_rn(v1.z, v1.w);
        *reinterpret_cast<uint4*>(g_x + i) = *reinterpret_cast<uint4*>(h);
    }
}

// ---------------------------------------------------------------------------
extern "C" void kernel_launch(void* const* d_in, const int* in_sizes, int n_in,
                              void* d_out, int out_size)
{
    (void)in_sizes; (void)n_in; (void)out_size;
    const float* x  = (const float*)d_in[0];
    const float* Wq = (const float*)d_in[1];
    const float* Wk = (const float*)d_in[2];
    const float* Wv = (const float*)d_in[3];
    float* out = (float*)d_out;

    cudaFuncSetAttribute(qkv_tc,    cudaFuncAttributeMaxDynamicSharedMemorySize, SMEM_BYTES);
    cudaFuncSetAttribute(scores_tc, cudaFuncAttributeMaxDynamicSharedMemorySize, SMEM_BYTES);
    cudaFuncSetAttribute(pv_tc,     cudaFuncAttributeMaxDynamicSharedMemorySize, SMEM_BYTES);

    // prep: z 0..2 = W transpose (needs 32x32 grid), z 3..6 = X convert
    // (4 x 1024 linear blocks; X has 8M halves = 4096 blocks x 256 thr x 8).
    prep<<<dim3(32, 32, 7), dim3(32, 8)>>>(x, Wq, Wk, Wv);
    qkv_tc<<<dim3(DD / TILE, (BB * SS) / TILE, 3), 256, SMEM_BYTES>>>();
    scores_tc<<<dim3(136, 1, BB), 256, SMEM_BYTES>>>();
    pv_tc<<<dim3(DD / TILE, SS / TILE, BB), 256, SMEM_BYTES>>>(out);
}

// round 15
// speedup vs baseline: 1.3847x; 1.0640x over previous
#include <cuda_runtime.h>
#include <cuda_fp16.h>
#include <cstdint>

// Problem constants
#define BB 4
#define SS 2048
#define DD 1024

// Scratch (allocation-free rule: __device__ globals). fp16 operands, fp32 sums.
__device__ __half g_x[BB * SS * DD];          // 16 MB  X in fp16
__device__ __half g_q[BB * SS * DD];          // 16 MB
__device__ __half g_k[BB * SS * DD];          // 16 MB
__device__ __half g_vt[BB * SS * DD];         // 16 MB (V^T per batch: [D, S])
__device__ __half g_wt[3 * DD * DD];          // 6 MB  (W^T)
__device__ __half g_p[(size_t)BB * SS * SS];  // 32 MB: unnormalized exp(scores)
__device__ float g_rs[(size_t)BB * SS * 16];  // per-row per-coltile partial sums

// ---------------------------------------------------------------------------
// fp16 mma.sync GEMM (f32 accum): C = A[M,K] * B[N,K]^T, A/B fp16 K-contig.
// Block 128x128, 256 threads (8 warps of 32x64), 2 CTAs/SM, KT=32 halves,
// 4-stage cp.async (prefetch distance 3), single __syncthreads per k-tile.
// R12 (bigger tile) and R13 (deeper pipeline) both regressed: this shape is
// the measured local optimum for mma.sync on this part. Do not perturb.
// ---------------------------------------------------------------------------
#define TILE 128
#define KT 32                                   // halves per stage
#define STAGES 4
#define ROWB 80                                 // bytes per row (64 data + 16 pad)
#define STAGE_BYTES (2 * TILE * ROWB)           // 20480
#define SMEM_BYTES (STAGES * STAGE_BYTES)       // 81920

#define EPI_HALF  0
#define EPI_EXP   1
#define EPI_SCALE 2
#define EPI_VT    3

__device__ __forceinline__ uint32_t smem_u32(const void* p) {
    uint32_t a;
    asm("{ .reg .u64 t; cvta.to.shared.u64 t, %1; cvt.u32.u64 %0, t; }"
        : "=r"(a) : "l"(p));
    return a;
}
__device__ __forceinline__ void cp16(uint32_t dst, const void* src) {
    asm volatile("cp.async.cg.shared.global [%0], [%1], 16;"
                 :: "r"(dst), "l"(src) : "memory");
}
__device__ __forceinline__ void ldsm4(uint32_t* d, uint32_t addr) {
    asm volatile("ldmatrix.sync.aligned.m8n8.x4.shared.b16 {%0,%1,%2,%3}, [%4];"
                 : "=r"(d[0]), "=r"(d[1]), "=r"(d[2]), "=r"(d[3]) : "r"(addr));
}
__device__ __forceinline__ void mma_f16(float* c, const uint32_t* a,
                                        uint32_t b0, uint32_t b1) {
    asm volatile(
        "mma.sync.aligned.m16n8k16.row.col.f32.f16.f16.f32 "
        "{%0,%1,%2,%3}, {%4,%5,%6,%7}, {%8,%9}, {%0,%1,%2,%3};"
        : "+f"(c[0]), "+f"(c[1]), "+f"(c[2]), "+f"(c[3])
        : "r"(a[0]), "r"(a[1]), "r"(a[2]), "r"(a[3]), "r"(b0), "r"(b1));
}

// EPI_VT: srow = s-offset within batch; ldC = SS; Cv pre-offset to batch.
// EPI_SCALE: rsp = g_rs + (b*SS + byt*128)*16, row partial base.
template<int EPI>
__device__ __forceinline__ void tc_gemm_body(
    const __half* __restrict__ A, const __half* __restrict__ B, void* __restrict__ Cv,
    int ldA, int ldB, int ldC, int kmax, int bm, int bn, char* smem,
    float* rs_out, const float* rsp, int srow)
{
    const int tid = threadIdx.x;        // 0..255
    const int wid = tid >> 5;           // 0..7
    const int lid = tid & 31;
    const int gid = lid >> 2;
    const int tq  = lid & 3;
    const int wm  = wid >> 1;           // 0..3 -> 32-row slice
    const int wn  = wid & 1;            // 0..1 -> 64-col half
    const uint32_t sb = smem_u32(smem);

    __shared__ float rsumv[TILE];
    if constexpr (EPI == EPI_SCALE) {
        // Cooperative row-reciprocal computation.
        if (tid < TILE) {
            const int ntl = kmax >> 7;          // tiles contributing to this row
            const float* p = rsp + (size_t)tid * 16;
            float s = 0.f;
            for (int t = 0; t < ntl; t++) s += p[t];
            rsumv[tid] = 1.f / s;
        }
    }

    // cp.async loader: thread -> (row = tid>>2 (+64j), 16B chunk = tid&3)
    const int lrow = tid >> 2;          // 0..63
    const int lch  = tid & 3;
    const __half* ag = A + (size_t)(bm + lrow) * ldA + lch * 8;
    const __half* bg = B + (size_t)(bn + lrow) * ldB + lch * 8;
    const uint32_t s_off = (uint32_t)(lrow * ROWB + lch * 16);

    const int nkt = kmax / KT;          // >= 4 always

    // Prologue: issue stages 0..STAGES-2 (3 in flight)
    #pragma unroll
    for (int s = 0; s < STAGES - 1; s++) {
        uint32_t da = sb + (uint32_t)s * STAGE_BYTES + s_off;
        uint32_t db = da + (uint32_t)TILE * ROWB;
        const __half* ag2 = ag + (size_t)s * KT;
        const __half* bg2 = bg + (size_t)s * KT;
        #pragma unroll
        for (int j = 0; j < 2; j++) {
            cp16(da + (uint32_t)(64 * j * ROWB), ag2 + (size_t)(64 * j) * ldA);
            cp16(db + (uint32_t)(64 * j * ROWB), bg2 + (size_t)(64 * j) * ldB);
        }
        asm volatile("cp.async.commit_group;" ::: "memory");
    }

    // ldmatrix lane addressing: sub&1 -> +8 rows, sub&2 -> +8 k halves (16B).
    const int sub = lid >> 3;
    const int rr  = lid & 7;
    const int rowsel = ((sub & 1) << 3) + rr;
    const uint32_t kselb = (uint32_t)((sub & 2) << 3);   // 0 or 16 bytes
    const uint32_t aL = (uint32_t)((wm * 32 + rowsel) * ROWB) + kselb;
    const uint32_t bL = (uint32_t)(TILE * ROWB) +
                        (uint32_t)((wn * 64 + rowsel) * ROWB) + kselb;

    float acc[2][8][4];
    #pragma unroll
    for (int mt = 0; mt < 2; mt++)
        #pragma unroll
        for (int nt = 0; nt < 8; nt++)
            #pragma unroll
            for (int r = 0; r < 4; r++) acc[mt][nt][r] = 0.f;

    for (int kt = 0; kt < nkt; kt++) {
        asm volatile("cp.async.wait_group %0;" :: "n"(STAGES - 2) : "memory");
        __syncthreads();

        // Issue-early prefetch of stage kt+STAGES-1.
        if (kt + STAGES - 1 < nkt) {
            const int s = kt + STAGES - 1;
            uint32_t da = sb + (uint32_t)(s % STAGES) * STAGE_BYTES + s_off;
            uint32_t db = da + (uint32_t)TILE * ROWB;
            const __half* ag2 = ag + (size_t)s * KT;
            const __half* bg2 = bg + (size_t)s * KT;
            #pragma unroll
            for (int j = 0; j < 2; j++) {
                cp16(da + (uint32_t)(64 * j * ROWB), ag2 + (size_t)(64 * j) * ldA);
                cp16(db + (uint32_t)(64 * j * ROWB), bg2 + (size_t)(64 * j) * ldB);
            }
        }
        asm volatile("cp.async.commit_group;" ::: "memory");

        const uint32_t sbase = sb + (uint32_t)(kt % STAGES) * STAGE_BYTES;
        #pragma unroll
        for (int ks = 0; ks < 2; ks++) {          // two k16 blocks per KT=32
            uint32_t af[2][4], bf[4][4];
            #pragma unroll
            for (int mt = 0; mt < 2; mt++)
                ldsm4(af[mt], sbase + aL + (uint32_t)(mt * 16 * ROWB) + ks * 32u);
            #pragma unroll
            for (int np = 0; np < 4; np++)
                ldsm4(bf[np], sbase + bL + (uint32_t)(np * 16 * ROWB) + ks * 32u);
            #pragma unroll
            for (int mt = 0; mt < 2; mt++)
                #pragma unroll
                for (int np = 0; np < 4; np++) {
                    mma_f16(acc[mt][2 * np],     af[mt], bf[np][0], bf[np][2]);
                    mma_f16(acc[mt][2 * np + 1], af[mt], bf[np][1], bf[np][3]);
                }
        }
    }

    // ------------------------------- Epilogues -------------------------------
    if constexpr (EPI == EPI_HALF) {
        __half* C = (__half*)Cv;
        #pragma unroll
        for (int mt = 0; mt < 2; mt++) {
            const int r0 = bm + wm * 32 + mt * 16 + gid;
            #pragma unroll
            for (int nt = 0; nt < 8; nt++) {
                const int c0 = bn + wn * 64 + nt * 8 + tq * 2;
                *reinterpret_cast<__half2*>(C + (size_t)r0 * ldC + c0) =
                    __floats2half2_rn(acc[mt][nt][0], acc[mt][nt][1]);
                *reinterpret_cast<__half2*>(C + (size_t)(r0 + 8) * ldC + c0) =
                    __floats2half2_rn(acc[mt][nt][2], acc[mt][nt][3]);
            }
        }
    }
    if constexpr (EPI == EPI_VT) {
        // Stage C tile (128x128 half) into smem as [col][row], then write
        // coalesced transposed rows to Cv (= g_vt batch base), ldC = SS.
        asm volatile("cp.async.wait_group 0;" ::: "memory");
        __syncthreads();                 // pipeline smem reuse is now safe
        __half* tb = (__half*)smem;      // [128][SPAD]
        const int SPAD = 136;            // halves; 272B row -> 16B-aligned rows
        #pragma unroll
        for (int mt = 0; mt < 2; mt++) {
            const int r0 = wm * 32 + mt * 16 + gid;     // local row
            #pragma unroll
            for (int nt = 0; nt < 8; nt++) {
                const int c0 = wn * 64 + nt * 8 + tq * 2;
                tb[(c0)     * SPAD + r0]     = __float2half_rn(acc[mt][nt][0]);
                tb[(c0 + 1) * SPAD + r0]     = __float2half_rn(acc[mt][nt][1]);
                tb[(c0)     * SPAD + r0 + 8] = __float2half_rn(acc[mt][nt][2]);
                tb[(c0 + 1) * SPAD + r0 + 8] = __float2half_rn(acc[mt][nt][3]);
            }
        }
        __syncthreads();
        __half* C = (__half*)Cv;
        const int d  = tid >> 1;                  // output row (D dim)
        const int s0 = (tid & 1) * 64;            // s-range half
        __half* orow = C + (size_t)(bn + d) * ldC + srow + s0;
        #pragma unroll
        for (int j = 0; j < 8; j++) {             // 8 x 8 halves = 64 halves
            *reinterpret_cast<uint4*>(orow + j * 8) =
                *reinterpret_cast<uint4*>(tb + d * SPAD + s0 + j * 8);
        }
    }
    if constexpr (EPI == EPI_EXP) {
        __half* C = (__half*)Cv;
        __shared__ float s2[2][TILE];
        const float inv = 0.03125f;         // 1/sqrt(1024)
        const bool diag = (bm == bn);
        #pragma unroll
        for (int mt = 0; mt < 2; mt++) {
            const int r0 = bm + wm * 32 + mt * 16 + gid;
            float sum0 = 0.f, sum1 = 0.f;
            #pragma unroll
            for (int nt = 0; nt < 8; nt++) {
                const int c0 = bn + wn * 64 + nt * 8 + tq * 2;
                __half h00 = __float2half_rn((!diag || c0     <= r0)     ? __expf(acc[mt][nt][0] * inv) : 0.f);
                __half h01 = __float2half_rn((!diag || c0 + 1 <= r0)     ? __expf(acc[mt][nt][1] * inv) : 0.f);
                __half h10 = __float2half_rn((!diag || c0     <= r0 + 8) ? __expf(acc[mt][nt][2] * inv) : 0.f);
                __half h11 = __float2half_rn((!diag || c0 + 1 <= r0 + 8) ? __expf(acc[mt][nt][3] * inv) : 0.f);
                *reinterpret_cast<__half2*>(C + (size_t)r0 * ldC + c0) = __halves2half2(h00, h01);
                *reinterpret_cast<__half2*>(C + (size_t)(r0 + 8) * ldC + c0) = __halves2half2(h10, h11);
                sum0 += __half2float(h00) + __half2float(h01);
                sum1 += __half2float(h10) + __half2float(h11);
            }
            #pragma unroll
            for (int off = 1; off <= 2; off <<= 1) {
                sum0 += __shfl_xor_sync(0xffffffffu, sum0, off);
                sum1 += __shfl_xor_sync(0xffffffffu, sum1, off);
            }
            if (tq == 0) {
                s2[wn][wm * 32 + mt * 16 + gid]     = sum0;
                s2[wn][wm * 32 + mt * 16 + gid + 8] = sum1;
            }
        }
        __syncthreads();
        if (tid < TILE)
            rs_out[(size_t)tid * 16] = s2[0][tid] + s2[1][tid];
    }
    if constexpr (EPI == EPI_SCALE) {
        float* C = (float*)Cv;
        #pragma unroll
        for (int mt = 0; mt < 2; mt++) {
            const int lr0 = wm * 32 + mt * 16 + gid;     // local row
            const int r0 = bm + lr0;
            const float sc0 = rsumv[lr0];
            const float sc1 = rsumv[lr0 + 8];
            #pragma unroll
            for (int nt = 0; nt < 8; nt++) {
                const int c0 = bn + wn * 64 + nt * 8 + tq * 2;
                *reinterpret_cast<float2*>(C + (size_t)r0 * ldC + c0) =
                    make_float2(acc[mt][nt][0] * sc0, acc[mt][nt][1] * sc0);
                *reinterpret_cast<float2*>(C + (size_t)(r0 + 8) * ldC + c0) =
                    make_float2(acc[mt][nt][2] * sc1, acc[mt][nt][3] * sc1);
            }
        }
    }
}

// ---------------------------------------------------------------------------
// GEMM kernel wrappers
// ---------------------------------------------------------------------------
__global__ __launch_bounds__(256, 2) void qkv_tc() {
    extern __shared__ __align__(16) char smem[];
    const int z = blockIdx.z;
    const __half* Bz = g_wt + (size_t)z * DD * DD;
    const int bm = blockIdx.y * TILE;
    if (z == 2) {
        // V: write transposed directly into g_vt (per-batch [D, S]).
        const int batch = bm >> 11;      // / SS
        const int srow  = bm & (SS - 1);
        tc_gemm_body<EPI_VT>(g_x, Bz, g_vt + (size_t)batch * SS * DD,
                             DD, DD, SS, DD, bm, blockIdx.x * TILE, smem,
                             nullptr, nullptr, srow);
    } else {
        __half* Cz = (z == 0) ? g_q : g_k;
        tc_gemm_body<EPI_HALF>(g_x, Bz, Cz, DD, DD, DD, DD,
                               bm, blockIdx.x * TILE, smem,
                               nullptr, nullptr, 0);
    }
}

// Only lower-triangle tiles: grid.x = 16*17/2 = 136 per batch.
__global__ __launch_bounds__(256, 2) void scores_tc() {
    extern __shared__ __align__(16) char smem[];
    const int t = blockIdx.x;
    int by = (int)((sqrtf(8.f * (float)t + 1.f) - 1.f) * 0.5f);
    while ((by + 1) * (by + 2) / 2 <= t) by++;
    while (by * (by + 1) / 2 > t) by--;
    const int bx = t - by * (by + 1) / 2;
    size_t b = blockIdx.z;
    float* rs = g_rs + ((size_t)(b * SS + by * TILE)) * 16 + bx;
    tc_gemm_body<EPI_EXP>(g_q + b * SS * DD, g_k + b * SS * DD,
                          g_p + b * (size_t)SS * SS, DD, DD, SS, DD,
                          by * TILE, bx * TILE, smem, rs, nullptr, 0);
}

// Globally heavy-first: y = byt_rank*4 + batch, byt = 15 - byt_rank.
// Dispatch order (x fastest, then y) starts all four batches' kmax=2048 rows
// in wave 1; light wedge tiles fill the tail.
__global__ __launch_bounds__(256, 2) void pv_tc(float* __restrict__ out) {
    extern __shared__ __align__(16) char smem[];
    const int y = blockIdx.y;                 // 0..63
    const size_t b = (size_t)(y & 3);
    const int byt = (SS / TILE - 1) - (y >> 2);
    const int kmax = (byt + 1) * TILE;        // 128..2048
    const float* rsp = g_rs + ((size_t)(b * SS + byt * TILE)) * 16;
    tc_gemm_body<EPI_SCALE>(g_p + b * (size_t)SS * SS, g_vt + b * SS * DD,
                            out + b * SS * DD, SS, SS, DD, kmax,
                            byt * TILE, blockIdx.x * TILE, smem,
                            nullptr, rsp, 0);
}

// ---------------------------------------------------------------------------
// Merged prologue: z<3 -> W^T transpose tile (fp32 -> fp16), z>=3 -> X convert.
// Both use 256 threads laid out as (32, 8).
// ---------------------------------------------------------------------------
__global__ void prep(const float* __restrict__ x,
                     const float* __restrict__ Wq,
                     const float* __restrict__ Wk,
                     const float* __restrict__ Wv) {
    const int z = blockIdx.z;
    if (z < 3) {
        const float* in = (z == 0) ? Wq : (z == 1) ? Wk : Wv;
        __half* out = g_wt + (size_t)z * DD * DD;
        __shared__ float t[32][33];
        const int tx = threadIdx.x, ty = threadIdx.y;
        const int bx = blockIdx.x * 32, by = blockIdx.y * 32;
        #pragma unroll
        for (int i = 0; i < 32; i += 8)
            t[ty + i][tx] = in[(size_t)(by + ty + i) * DD + bx + tx];
        __syncthreads();
        #pragma unroll
        for (int i = 0; i < 32; i += 8)
            out[(size_t)(bx + ty + i) * DD + by + tx] = __float2half_rn(t[tx][ty + i]);
    } else {
        // X convert: linear block id over (z-3, blockIdx.y, blockIdx.x).
        const int blk = (z - 3) * 1024 + blockIdx.y * 32 + blockIdx.x;
        const int tid = threadIdx.y * 32 + threadIdx.x;
        const size_t i = ((size_t)blk * 256 + tid) * 8;
        float4 v0 = *reinterpret_cast<const float4*>(x + i);
        float4 v1 = *reinterpret_cast<const float4*>(x + i + 4);
        __half2 h[4];
        h[0] = __floats2half2_rn(v0.x, v0.y);
        h[1] = __floats2half2_rn(v0.z, v0.w);
        h[2] = __floats2half2_rn(v1.x, v1.y);
        h[3] = __floats2half2_rn(v1.z, v1.w);
        *reinterpret_cast<uint4*>(g_x + i) = *reinterpret_cast<uint4*>(h);
    }
}

// ---------------------------------------------------------------------------
extern "C" void kernel_launch(void* const* d_in, const int* in_sizes, int n_in,
                              void* d_out, int out_size)
{
    (void)in_sizes; (void)n_in; (void)out_size;
    const float* x  = (const float*)d_in[0];
    const float* Wq = (const float*)d_in[1];
    const float* Wk = (const float*)d_in[2];
    const float* Wv = (const float*)d_in[3];
    float* out = (float*)d_out;

    cudaFuncSetAttribute(qkv_tc,    cudaFuncAttributeMaxDynamicSharedMemorySize, SMEM_BYTES);
    cudaFuncSetAttribute(scores_tc, cudaFuncAttributeMaxDynamicSharedMemorySize, SMEM_BYTES);
    cudaFuncSetAttribute(pv_tc,     cudaFuncAttributeMaxDynamicSharedMemorySize, SMEM_BYTES);

    // prep: z 0..2 = W transpose (needs 32x32 grid), z 3..6 = X convert
    // (4 x 1024 linear blocks; X has 8M halves = 4096 blocks x 256 thr x 8).
    prep<<<dim3(32, 32, 7), dim3(32, 8)>>>(x, Wq, Wk, Wv);
    qkv_tc<<<dim3(DD / TILE, (BB * SS) / TILE, 3), 256, SMEM_BYTES>>>();
    scores_tc<<<dim3(136, 1, BB), 256, SMEM_BYTES>>>();
    pv_tc<<<dim3(DD / TILE, (SS / TILE) * BB, 1), 256, SMEM_BYTES>>>(out);
}

// round 16
// speedup vs baseline: 1.4498x; 1.0471x over previous
#include <cuda_runtime.h>
#include <cuda_fp16.h>
#include <cstdint>

// Problem constants
#define BB 4
#define SS 2048
#define DD 1024

// Scratch (allocation-free rule: __device__ globals). fp16 operands, fp32 sums.
__device__ __half g_x[BB * SS * DD];          // 16 MB  X in fp16
__device__ __half g_q[BB * SS * DD];          // 16 MB
__device__ __half g_k[BB * SS * DD];          // 16 MB
__device__ __half g_vt[BB * SS * DD];         // 16 MB (V^T per batch: [D, S])
__device__ __half g_wt[3 * DD * DD];          // 6 MB  (W^T)
__device__ __half g_p[(size_t)BB * SS * SS];  // 32 MB: unnormalized exp(scores)
__device__ float g_rs[(size_t)BB * SS * 16];  // per-row per-coltile partial sums

// ---------------------------------------------------------------------------
// fp16 mma.sync GEMM (f32 accum): C = A[M,K] * B[N,K]^T, A/B fp16 K-contig.
// Block 128x128, 256 threads (8 warps of 32x64), 2 CTAs/SM, KT=32 halves,
// 4-stage cp.async (prefetch distance 3), single __syncthreads per k-tile.
// R12 (bigger tile) and R13 (deeper pipeline) both regressed: this shape is
// the measured local optimum for mma.sync on this part. Do not perturb.
// ---------------------------------------------------------------------------
#define TILE 128
#define KT 32                                   // halves per stage
#define STAGES 4
#define ROWB 80                                 // bytes per row (64 data + 16 pad)
#define STAGE_BYTES (2 * TILE * ROWB)           // 20480
#define SMEM_BYTES (STAGES * STAGE_BYTES)       // 81920

#define EPI_HALF  0
#define EPI_EXP   1
#define EPI_SCALE 2
#define EPI_VT    3

__device__ __forceinline__ uint32_t smem_u32(const void* p) {
    uint32_t a;
    asm("{ .reg .u64 t; cvta.to.shared.u64 t, %1; cvt.u32.u64 %0, t; }"
        : "=r"(a) : "l"(p));
    return a;
}
__device__ __forceinline__ void cp16(uint32_t dst, const void* src) {
    asm volatile("cp.async.cg.shared.global [%0], [%1], 16;"
                 :: "r"(dst), "l"(src) : "memory");
}
__device__ __forceinline__ void ldsm4(uint32_t* d, uint32_t addr) {
    asm volatile("ldmatrix.sync.aligned.m8n8.x4.shared.b16 {%0,%1,%2,%3}, [%4];"
                 : "=r"(d[0]), "=r"(d[1]), "=r"(d[2]), "=r"(d[3]) : "r"(addr));
}
__device__ __forceinline__ void mma_f16(float* c, const uint32_t* a,
                                        uint32_t b0, uint32_t b1) {
    asm volatile(
        "mma.sync.aligned.m16n8k16.row.col.f32.f16.f16.f32 "
        "{%0,%1,%2,%3}, {%4,%5,%6,%7}, {%8,%9}, {%0,%1,%2,%3};"
        : "+f"(c[0]), "+f"(c[1]), "+f"(c[2]), "+f"(c[3])
        : "r"(a[0]), "r"(a[1]), "r"(a[2]), "r"(a[3]), "r"(b0), "r"(b1));
}

// EPI_VT: srow = s-offset within batch; ldC = SS; Cv pre-offset to batch.
// EPI_SCALE: rsp = g_rs + (b*SS + byt*128)*16, row partial base.
template<int EPI>
__device__ __forceinline__ void tc_gemm_body(
    const __half* __restrict__ A, const __half* __restrict__ B, void* __restrict__ Cv,
    int ldA, int ldB, int ldC, int kmax, int bm, int bn, char* smem,
    float* rs_out, const float* rsp, int srow)
{
    const int tid = threadIdx.x;        // 0..255
    const int wid = tid >> 5;           // 0..7
    const int lid = tid & 31;
    const int gid = lid >> 2;
    const int tq  = lid & 3;
    const int wm  = wid >> 1;           // 0..3 -> 32-row slice
    const int wn  = wid & 1;            // 0..1 -> 64-col half
    const uint32_t sb = smem_u32(smem);

    __shared__ float rsumv[TILE];
    if constexpr (EPI == EPI_SCALE) {
        // Cooperative row-reciprocal computation.
        if (tid < TILE) {
            const int ntl = kmax >> 7;          // tiles contributing to this row
            const float* p = rsp + (size_t)tid * 16;
            float s = 0.f;
            for (int t = 0; t < ntl; t++) s += p[t];
            rsumv[tid] = 1.f / s;
        }
    }

    // cp.async loader: thread -> (row = tid>>2 (+64j), 16B chunk = tid&3)
    const int lrow = tid >> 2;          // 0..63
    const int lch  = tid & 3;
    const __half* ag = A + (size_t)(bm + lrow) * ldA + lch * 8;
    const __half* bg = B + (size_t)(bn + lrow) * ldB + lch * 8;
    const uint32_t s_off = (uint32_t)(lrow * ROWB + lch * 16);

    const int nkt = kmax / KT;          // >= 4 always

    // Prologue: issue stages 0..STAGES-2 (3 in flight)
    #pragma unroll
    for (int s = 0; s < STAGES - 1; s++) {
        uint32_t da = sb + (uint32_t)s * STAGE_BYTES + s_off;
        uint32_t db = da + (uint32_t)TILE * ROWB;
        const __half* ag2 = ag + (size_t)s * KT;
        const __half* bg2 = bg + (size_t)s * KT;
        #pragma unroll
        for (int j = 0; j < 2; j++) {
            cp16(da + (uint32_t)(64 * j * ROWB), ag2 + (size_t)(64 * j) * ldA);
            cp16(db + (uint32_t)(64 * j * ROWB), bg2 + (size_t)(64 * j) * ldB);
        }
        asm volatile("cp.async.commit_group;" ::: "memory");
    }

    // ldmatrix lane addressing: sub&1 -> +8 rows, sub&2 -> +8 k halves (16B).
    const int sub = lid >> 3;
    const int rr  = lid & 7;
    const int rowsel = ((sub & 1) << 3) + rr;
    const uint32_t kselb = (uint32_t)((sub & 2) << 3);   // 0 or 16 bytes
    const uint32_t aL = (uint32_t)((wm * 32 + rowsel) * ROWB) + kselb;
    const uint32_t bL = (uint32_t)(TILE * ROWB) +
                        (uint32_t)((wn * 64 + rowsel) * ROWB) + kselb;

    float acc[2][8][4];
    #pragma unroll
    for (int mt = 0; mt < 2; mt++)
        #pragma unroll
        for (int nt = 0; nt < 8; nt++)
            #pragma unroll
            for (int r = 0; r < 4; r++) acc[mt][nt][r] = 0.f;

    for (int kt = 0; kt < nkt; kt++) {
        asm volatile("cp.async.wait_group %0;" :: "n"(STAGES - 2) : "memory");
        __syncthreads();

        // Issue-early prefetch of stage kt+STAGES-1.
        if (kt + STAGES - 1 < nkt) {
            const int s = kt + STAGES - 1;
            uint32_t da = sb + (uint32_t)(s % STAGES) * STAGE_BYTES + s_off;
            uint32_t db = da + (uint32_t)TILE * ROWB;
            const __half* ag2 = ag + (size_t)s * KT;
            const __half* bg2 = bg + (size_t)s * KT;
            #pragma unroll
            for (int j = 0; j < 2; j++) {
                cp16(da + (uint32_t)(64 * j * ROWB), ag2 + (size_t)(64 * j) * ldA);
                cp16(db + (uint32_t)(64 * j * ROWB), bg2 + (size_t)(64 * j) * ldB);
            }
        }
        asm volatile("cp.async.commit_group;" ::: "memory");

        const uint32_t sbase = sb + (uint32_t)(kt % STAGES) * STAGE_BYTES;
        #pragma unroll
        for (int ks = 0; ks < 2; ks++) {          // two k16 blocks per KT=32
            uint32_t af[2][4], bf[4][4];
            #pragma unroll
            for (int mt = 0; mt < 2; mt++)
                ldsm4(af[mt], sbase + aL + (uint32_t)(mt * 16 * ROWB) + ks * 32u);
            #pragma unroll
            for (int np = 0; np < 4; np++)
                ldsm4(bf[np], sbase + bL + (uint32_t)(np * 16 * ROWB) + ks * 32u);
            #pragma unroll
            for (int mt = 0; mt < 2; mt++)
                #pragma unroll
                for (int np = 0; np < 4; np++) {
                    mma_f16(acc[mt][2 * np],     af[mt], bf[np][0], bf[np][2]);
                    mma_f16(acc[mt][2 * np + 1], af[mt], bf[np][1], bf[np][3]);
                }
        }
    }

    // ------------------------------- Epilogues -------------------------------
    if constexpr (EPI == EPI_HALF) {
        __half* C = (__half*)Cv;
        #pragma unroll
        for (int mt = 0; mt < 2; mt++) {
            const int r0 = bm + wm * 32 + mt * 16 + gid;
            #pragma unroll
            for (int nt = 0; nt < 8; nt++) {
                const int c0 = bn + wn * 64 + nt * 8 + tq * 2;
                *reinterpret_cast<__half2*>(C + (size_t)r0 * ldC + c0) =
                    __floats2half2_rn(acc[mt][nt][0], acc[mt][nt][1]);
                *reinterpret_cast<__half2*>(C + (size_t)(r0 + 8) * ldC + c0) =
                    __floats2half2_rn(acc[mt][nt][2], acc[mt][nt][3]);
            }
        }
    }
    if constexpr (EPI == EPI_VT) {
        // Stage C tile (128x128 half) into smem as [col][row], then write
        // coalesced transposed rows to Cv (= g_vt batch base), ldC = SS.
        asm volatile("cp.async.wait_group 0;" ::: "memory");
        __syncthreads();                 // pipeline smem reuse is now safe
        __half* tb = (__half*)smem;      // [128][SPAD]
        const int SPAD = 136;            // halves; 272B row -> 16B-aligned rows
        #pragma unroll
        for (int mt = 0; mt < 2; mt++) {
            const int r0 = wm * 32 + mt * 16 + gid;     // local row
            #pragma unroll
            for (int nt = 0; nt < 8; nt++) {
                const int c0 = wn * 64 + nt * 8 + tq * 2;
                tb[(c0)     * SPAD + r0]     = __float2half_rn(acc[mt][nt][0]);
                tb[(c0 + 1) * SPAD + r0]     = __float2half_rn(acc[mt][nt][1]);
                tb[(c0)     * SPAD + r0 + 8] = __float2half_rn(acc[mt][nt][2]);
                tb[(c0 + 1) * SPAD + r0 + 8] = __float2half_rn(acc[mt][nt][3]);
            }
        }
        __syncthreads();
        __half* C = (__half*)Cv;
        const int d  = tid >> 1;                  // output row (D dim)
        const int s0 = (tid & 1) * 64;            // s-range half
        __half* orow = C + (size_t)(bn + d) * ldC + srow + s0;
        #pragma unroll
        for (int j = 0; j < 8; j++) {             // 8 x 8 halves = 64 halves
            *reinterpret_cast<uint4*>(orow + j * 8) =
                *reinterpret_cast<uint4*>(tb + d * SPAD + s0 + j * 8);
        }
    }
    if constexpr (EPI == EPI_EXP) {
        __half* C = (__half*)Cv;
        __shared__ float s2[2][TILE];
        const float inv = 0.03125f;         // 1/sqrt(1024)
        const bool diag = (bm == bn);
        #pragma unroll
        for (int mt = 0; mt < 2; mt++) {
            const int r0 = bm + wm * 32 + mt * 16 + gid;
            float sum0 = 0.f, sum1 = 0.f;
            #pragma unroll
            for (int nt = 0; nt < 8; nt++) {
                const int c0 = bn + wn * 64 + nt * 8 + tq * 2;
                __half h00 = __float2half_rn((!diag || c0     <= r0)     ? __expf(acc[mt][nt][0] * inv) : 0.f);
                __half h01 = __float2half_rn((!diag || c0 + 1 <= r0)     ? __expf(acc[mt][nt][1] * inv) : 0.f);
                __half h10 = __float2half_rn((!diag || c0     <= r0 + 8) ? __expf(acc[mt][nt][2] * inv) : 0.f);
                __half h11 = __float2half_rn((!diag || c0 + 1 <= r0 + 8) ? __expf(acc[mt][nt][3] * inv) : 0.f);
                *reinterpret_cast<__half2*>(C + (size_t)r0 * ldC + c0) = __halves2half2(h00, h01);
                *reinterpret_cast<__half2*>(C + (size_t)(r0 + 8) * ldC + c0) = __halves2half2(h10, h11);
                sum0 += __half2float(h00) + __half2float(h01);
                sum1 += __half2float(h10) + __half2float(h11);
            }
            #pragma unroll
            for (int off = 1; off <= 2; off <<= 1) {
                sum0 += __shfl_xor_sync(0xffffffffu, sum0, off);
                sum1 += __shfl_xor_sync(0xffffffffu, sum1, off);
            }
            if (tq == 0) {
                s2[wn][wm * 32 + mt * 16 + gid]     = sum0;
                s2[wn][wm * 32 + mt * 16 + gid + 8] = sum1;
            }
        }
        __syncthreads();
        if (tid < TILE)
            rs_out[(size_t)tid * 16] = s2[0][tid] + s2[1][tid];
    }
    if constexpr (EPI == EPI_SCALE) {
        float* C = (float*)Cv;
        #pragma unroll
        for (int mt = 0; mt < 2; mt++) {
            const int lr0 = wm * 32 + mt * 16 + gid;     // local row
            const int r0 = bm + lr0;
            const float sc0 = rsumv[lr0];
            const float sc1 = rsumv[lr0 + 8];
            #pragma unroll
            for (int nt = 0; nt < 8; nt++) {
                const int c0 = bn + wn * 64 + nt * 8 + tq * 2;
                *reinterpret_cast<float2*>(C + (size_t)r0 * ldC + c0) =
                    make_float2(acc[mt][nt][0] * sc0, acc[mt][nt][1] * sc0);
                *reinterpret_cast<float2*>(C + (size_t)(r0 + 8) * ldC + c0) =
                    make_float2(acc[mt][nt][2] * sc1, acc[mt][nt][3] * sc1);
            }
        }
    }
}

// ---------------------------------------------------------------------------
// GEMM kernel wrappers
// ---------------------------------------------------------------------------
// Q and K projections only (V moved into scores_v_tc to fill its waves).
__global__ __launch_bounds__(256, 2) void qk_tc() {
    extern __shared__ __align__(16) char smem[];
    const int z = blockIdx.z;                      // 0 = Q, 1 = K
    const __half* Bz = g_wt + (size_t)z * DD * DD;
    __half* Cz = (z == 0) ? g_q : g_k;
    tc_gemm_body<EPI_HALF>(g_x, Bz, Cz, DD, DD, DD, DD,
                           blockIdx.y * TILE, blockIdx.x * TILE, smem,
                           nullptr, nullptr, 0);
}

// Fused: blocks 0..511 = V projection (writes g_vt transposed), blocks
// 512..1055 = scores lower-triangle tiles (136 per batch). Uniform K=1024
// work -> 1056 blocks pack into ~3.6 waves instead of two tail-wasting grids.
__global__ __launch_bounds__(256, 2) void scores_v_tc() {
    extern __shared__ __align__(16) char smem[];
    const int t = blockIdx.x;
    if (t < 512) {
        // V projection tile: bn = d-tile, bm = global s-row tile.
        const int bn = (t & 7) * TILE;
        const int bm = (t >> 3) * TILE;
        const int batch = bm >> 11;                // / SS
        const int srow  = bm & (SS - 1);
        tc_gemm_body<EPI_VT>(g_x, g_wt + (size_t)2 * DD * DD,
                             g_vt + (size_t)batch * SS * DD,
                             DD, DD, SS, DD, bm, bn, smem,
                             nullptr, nullptr, srow);
    } else {
        const int ts = t - 512;                    // 0..543
        const int b  = ts / 136;
        const int tt = ts - b * 136;
        int by = (int)((sqrtf(8.f * (float)tt + 1.f) - 1.f) * 0.5f);
        while ((by + 1) * (by + 2) / 2 <= tt) by++;
        while (by * (by + 1) / 2 > tt) by--;
        const int bx = tt - by * (by + 1) / 2;
        float* rs = g_rs + ((size_t)((size_t)b * SS + by * TILE)) * 16 + bx;
        tc_gemm_body<EPI_EXP>(g_q + (size_t)b * SS * DD, g_k + (size_t)b * SS * DD,
                              g_p + (size_t)b * SS * SS, DD, DD, SS, DD,
                              by * TILE, bx * TILE, smem, rs, nullptr, 0);
    }
}

// Globally heavy-first: y = byt_rank*4 + batch, byt = 15 - byt_rank.
// Dispatch order (x fastest, then y) starts all four batches' kmax=2048 rows
// in wave 1; light wedge tiles fill the tail.
__global__ __launch_bounds__(256, 2) void pv_tc(float* __restrict__ out) {
    extern __shared__ __align__(16) char smem[];
    const int y = blockIdx.y;                 // 0..63
    const size_t b = (size_t)(y & 3);
    const int byt = (SS / TILE - 1) - (y >> 2);
    const int kmax = (byt + 1) * TILE;        // 128..2048
    const float* rsp = g_rs + ((size_t)(b * SS + byt * TILE)) * 16;
    tc_gemm_body<EPI_SCALE>(g_p + b * (size_t)SS * SS, g_vt + b * SS * DD,
                            out + b * SS * DD, SS, SS, DD, kmax,
                            byt * TILE, blockIdx.x * TILE, smem,
                            nullptr, rsp, 0);
}

// ---------------------------------------------------------------------------
// Merged prologue: z<3 -> W^T transpose tile (fp32 -> fp16), z>=3 -> X convert.
// Both use 256 threads laid out as (32, 8).
// ---------------------------------------------------------------------------
__global__ void prep(const float* __restrict__ x,
                     const float* __restrict__ Wq,
                     const float* __restrict__ Wk,
                     const float* __restrict__ Wv) {
    const int z = blockIdx.z;
    if (z < 3) {
        const float* in = (z == 0) ? Wq : (z == 1) ? Wk : Wv;
        __half* out = g_wt + (size_t)z * DD * DD;
        __shared__ float t[32][33];
        const int tx = threadIdx.x, ty = threadIdx.y;
        const int bx = blockIdx.x * 32, by = blockIdx.y * 32;
        #pragma unroll
        for (int i = 0; i < 32; i += 8)
            t[ty + i][tx] = in[(size_t)(by + ty + i) * DD + bx + tx];
        __syncthreads();
        #pragma unroll
        for (int i = 0; i < 32; i += 8)
            out[(size_t)(bx + ty + i) * DD + by + tx] = __float2half_rn(t[tx][ty + i]);
    } else {
        // X convert: linear block id over (z-3, blockIdx.y, blockIdx.x).
        const int blk = (z - 3) * 1024 + blockIdx.y * 32 + blockIdx.x;
        const int tid = threadIdx.y * 32 + threadIdx.x;
        const size_t i = ((size_t)blk * 256 + tid) * 8;
        float4 v0 = *reinterpret_cast<const float4*>(x + i);
        float4 v1 = *reinterpret_cast<const float4*>(x + i + 4);
        __half2 h[4];
        h[0] = __floats2half2_rn(v0.x, v0.y);
        h[1] = __floats2half2_rn(v0.z, v0.w);
        h[2] = __floats2half2_rn(v1.x, v1.y);
        h[3] = __floats2half2_rn(v1.z, v1.w);
        *reinterpret_cast<uint4*>(g_x + i) = *reinterpret_cast<uint4*>(h);
    }
}

// ---------------------------------------------------------------------------
extern "C" void kernel_launch(void* const* d_in, const int* in_sizes, int n_in,
                              void* d_out, int out_size)
{
    (void)in_sizes; (void)n_in; (void)out_size;
    const float* x  = (const float*)d_in[0];
    const float* Wq = (const float*)d_in[1];
    const float* Wk = (const float*)d_in[2];
    const float* Wv = (const float*)d_in[3];
    float* out = (float*)d_out;

    cudaFuncSetAttribute(qk_tc,       cudaFuncAttributeMaxDynamicSharedMemorySize, SMEM_BYTES);
    cudaFuncSetAttribute(scores_v_tc, cudaFuncAttributeMaxDynamicSharedMemorySize, SMEM_BYTES);
    cudaFuncSetAttribute(pv_tc,       cudaFuncAttributeMaxDynamicSharedMemorySize, SMEM_BYTES);

    // prep: z 0..2 = W transpose (needs 32x32 grid), z 3..6 = X convert
    // (4 x 1024 linear blocks; X has 8M halves = 4096 blocks x 256 thr x 8).
    prep<<<dim3(32, 32, 7), dim3(32, 8)>>>(x, Wq, Wk, Wv);
    qk_tc<<<dim3(DD / TILE, (BB * SS) / TILE, 2), 256, SMEM_BYTES>>>();
    scores_v_tc<<<dim3(512 + 136 * BB), 256, SMEM_BYTES>>>();
    pv_tc<<<dim3(DD / TILE, (SS / TILE) * BB, 1), 256, SMEM_BYTES>>>(out);
}